// round 6
// baseline (speedup 1.0000x reference)
#include <cuda_runtime.h>
#include <cuda_bf16.h>
#include <math.h>

#define NN 160
#define EE 256
#define HH 4
#define DD 64
#define ROWS (NN*NN)          // 25600
#define PC 784                // packed projection cols
#define SCALE 0.125f
#define LN_EPS 1e-5f

// column offsets in packed projection
#define C_QIN   0
#define C_KIN   256
#define C_VIN   320
#define C_EGIN  384
#define C_QOUT  392
#define C_KOUT  648
#define C_VOUT  712
#define C_EGOUT 776

typedef unsigned long long u64;

// -------------------- f32x2 packed helpers (sm_10x) ------------------------
__device__ __forceinline__ void fma2(u64 &d, u64 a, u64 b) {
    asm("fma.rn.f32x2 %0, %1, %2, %3;" : "=l"(d) : "l"(a), "l"(b), "l"(d));
}
__device__ __forceinline__ u64 pk2(float x, float y) {
    u64 r;
    asm("mov.b64 %0, {%1, %2};" : "=l"(r) : "r"(__float_as_uint(x)), "r"(__float_as_uint(y)));
    return r;
}
__device__ __forceinline__ void up2(u64 a, float &x, float &y) {
    unsigned lo, hi;
    asm("mov.b64 {%0, %1}, %2;" : "=r"(lo), "=r"(hi) : "l"(a));
    x = __uint_as_float(lo); y = __uint_as_float(hi);
}

// -------------------- scratch ----------------------------------------------
__device__ float g_eln[ROWS * EE];
__device__ float g_proj[ROWS * PC];
__device__ float g_va[ROWS * 512];
__device__ float g_wcat[EE * PC];
__device__ float g_bcat[PC];

// -------------------- block reduce helper (256 threads) --------------------
__device__ __forceinline__ float block_sum256(float v) {
    __shared__ float red[8];
    __shared__ float tot;
    #pragma unroll
    for (int o = 16; o; o >>= 1) v += __shfl_xor_sync(~0u, v, o);
    int wid = threadIdx.x >> 5, lane = threadIdx.x & 31;
    if (lane == 0) red[wid] = v;
    __syncthreads();
    float s = (lane < 8) ? red[lane] : 0.f;
    #pragma unroll
    for (int o = 4; o; o >>= 1) s += __shfl_xor_sync(~0u, s, o);
    if (threadIdx.x == 0) tot = s;
    __syncthreads();
    return tot;
}

// -------------------- LayerNorm --------------------------------------------
__global__ void ln_kernel(const float* __restrict__ e,
                          const float* __restrict__ g,
                          const float* __restrict__ b) {
    int r = blockIdx.x;
    int c = threadIdx.x;
    float x = e[(size_t)r * EE + c];
    float mu = block_sum256(x) * (1.f / EE);
    float dx = x - mu;
    float var = block_sum256(dx * dx) * (1.f / EE);
    g_eln[(size_t)r * EE + c] = dx * rsqrtf(var + LN_EPS) * g[c] + b[c];
}

// -------------------- pack weights (fold SCALE into Q) ----------------------
__global__ void pack_kernel(const float* __restrict__ Wq_in,  const float* __restrict__ bq_in,
                            const float* __restrict__ Wkv_in, const float* __restrict__ bkv_in,
                            const float* __restrict__ Weg_in, const float* __restrict__ beg_in,
                            const float* __restrict__ Wq_out, const float* __restrict__ bq_out,
                            const float* __restrict__ Wkv_out,const float* __restrict__ bkv_out,
                            const float* __restrict__ Weg_out,const float* __restrict__ beg_out) {
    int k = blockIdx.x; // 0..255
    for (int c = threadIdx.x; c < PC; c += blockDim.x) {
        float w, bb;
        if (c < 256)      { w = Wq_in [k*256 +  c      ]*SCALE; bb = bq_in [c      ]*SCALE; }
        else if (c < 384) { w = Wkv_in[k*128 + (c-256) ];       bb = bkv_in[c-256  ]; }
        else if (c < 392) { w = Weg_in[k*8   + (c-384) ];       bb = beg_in[c-384  ]; }
        else if (c < 648) { w = Wq_out[k*256 + (c-392) ]*SCALE; bb = bq_out[c-392  ]*SCALE; }
        else if (c < 776) { w = Wkv_out[k*128+ (c-648) ];       bb = bkv_out[c-648 ]; }
        else              { w = Weg_out[k*8  + (c-776) ];       bb = beg_out[c-776 ]; }
        g_wcat[k*PC + c] = w;
        if (k == 0) g_bcat[c] = bb;
    }
}

// -------------------- SGEMM 128x128x16, 256 threads, 8x8 f32x2 --------------
__global__ __launch_bounds__(256, 2)
void sgemm_bias(const float* __restrict__ A, const float* __restrict__ B,
                const float* __restrict__ bias, float* __restrict__ C,
                int M, int N, int K) {
    const int BM = 128, BN = 128, BK = 16;
    __shared__ float As[BK][BM + 4];
    __shared__ float Bs[BK][BN + 4];
    int tid = threadIdx.x;
    int tr = tid >> 4;      // 0..15
    int tc = tid & 15;      // 0..15
    int bm = blockIdx.y * BM;
    int bn = blockIdx.x * BN;
    // acc: m-pairs x 8 n : accp[mp][n] = (C[tr*8+2mp][n], C[tr*8+2mp+1][n])
    u64 accp[4][8];
    #pragma unroll
    for (int mp = 0; mp < 4; mp++)
        #pragma unroll
        for (int n = 0; n < 8; n++) accp[mp][n] = 0ull;

    for (int k0 = 0; k0 < K; k0 += BK) {
        #pragma unroll
        for (int l = 0; l < 2; l++) {
            int i = tid * 2 + l;               // 0..511
            int row = i >> 2;                  // 0..127
            int kq = (i & 3) * 4;              // 0,4,8,12
            float4 v = *(const float4*)(A + (size_t)(bm + row) * K + k0 + kq);
            As[kq + 0][row] = v.x; As[kq + 1][row] = v.y;
            As[kq + 2][row] = v.z; As[kq + 3][row] = v.w;
        }
        #pragma unroll
        for (int l = 0; l < 2; l++) {
            int i = tid + l * 256;             // 0..511
            int row = i >> 5;                  // 0..15
            int cq = (i & 31) * 4;             // 0..124
            float4 v = make_float4(0.f, 0.f, 0.f, 0.f);
            if (bn + cq < N)
                v = *(const float4*)(B + (size_t)(k0 + row) * N + bn + cq);
            *(float4*)&Bs[row][cq] = v;
        }
        __syncthreads();
        #pragma unroll
        for (int kk = 0; kk < BK; kk++) {
            const u64* ap = (const u64*)&As[kk][tr * 8];
            u64 a0 = ap[0], a1 = ap[1], a2 = ap[2], a3 = ap[3];
            float4 b0 = *(const float4*)&Bs[kk][tc * 8];
            float4 b1 = *(const float4*)&Bs[kk][tc * 8 + 4];
            u64 bd[8];
            bd[0] = pk2(b0.x, b0.x); bd[1] = pk2(b0.y, b0.y);
            bd[2] = pk2(b0.z, b0.z); bd[3] = pk2(b0.w, b0.w);
            bd[4] = pk2(b1.x, b1.x); bd[5] = pk2(b1.y, b1.y);
            bd[6] = pk2(b1.z, b1.z); bd[7] = pk2(b1.w, b1.w);
            #pragma unroll
            for (int n = 0; n < 8; n++) {
                fma2(accp[0][n], a0, bd[n]);
                fma2(accp[1][n], a1, bd[n]);
                fma2(accp[2][n], a2, bd[n]);
                fma2(accp[3][n], a3, bd[n]);
            }
        }
        __syncthreads();
    }
    #pragma unroll
    for (int mp = 0; mp < 4; mp++) {
        int row0 = bm + tr * 8 + 2 * mp;
        #pragma unroll
        for (int n = 0; n < 8; n++) {
            int col = bn + tc * 8 + n;
            if (col < N) {
                float x0, x1; up2(accp[mp][n], x0, x1);
                float bz = bias[col];
                C[(size_t)row0 * N + col]       = x0 + bz;
                C[(size_t)(row0 + 1) * N + col] = x1 + bz;
            }
        }
    }
}

// -------------------- quad-cooperative flash attention ----------------------
// block = (j, ic, br); 128 threads; thread (il = tid>>2, dq = tid&3) owns
// d in {8u+2dq, 8u+2dq+1} for ALL 4 heads of row i = ic*32+il.
// K/V staged in 16-k chunks (8KB smem), reg double-buffered.
// Softmax without max-subtraction (logits provably tiny for this problem).
__global__ __launch_bounds__(128, 2)
void attn_flash(const float* __restrict__ proj, const float* __restrict__ mask,
                float* __restrict__ va) {
    __shared__ float kv[16 * 128];
    const int j  = blockIdx.x;
    const int ic = blockIdx.y;
    const int br = blockIdx.z;            // 0 = in, 1 = out
    const int tid = threadIdx.x;
    const int il = tid >> 2, dq = tid & 3;
    const int i  = ic * 32 + il;
    const int KVB = br ? C_KOUT : C_KIN;
    const int QB  = br ? C_QOUT : C_QIN;
    const int EGB = br ? C_EGOUT : C_EGIN;

    // Q for all 4 heads, d-pairs of this dq
    u64 q[4][8];
    {
        const float* qp = proj + (size_t)(i * NN + j) * PC + QB;
        #pragma unroll
        for (int h = 0; h < 4; h++)
            #pragma unroll
            for (int u = 0; u < 8; u++) {
                int d0 = 8 * u + 2 * dq;
                q[h][u] = pk2(qp[d0 * 4 + h], qp[(d0 + 1) * 4 + h]);
            }
    }
    u64 acc[4][8];
    #pragma unroll
    for (int h = 0; h < 4; h++)
        #pragma unroll
        for (int u = 0; u < 8; u++) acc[h][u] = 0ull;
    float s0 = 0.f, s1 = 0.f, s2 = 0.f, s3 = 0.f;

    // prefetch chunk 0 (16 k x 128 floats; 4 float4 per thread)
    float4 pf[4];
    #pragma unroll
    for (int l = 0; l < 4; l++) {
        int slot = tid + l * 128;
        int k = slot >> 5, c = slot & 31;
        int row = br ? (k * NN + j) : (j * NN + k);
        pf[l] = *(const float4*)(proj + (size_t)row * PC + KVB + c * 4);
    }

    for (int t = 0; t < 10; t++) {
        #pragma unroll
        for (int l = 0; l < 4; l++) {
            int slot = tid + l * 128;
            *(float4*)&kv[(slot >> 5) * 128 + (slot & 31) * 4] = pf[l];
        }
        __syncthreads();
        if (t < 9) {
            #pragma unroll
            for (int l = 0; l < 4; l++) {
                int slot = tid + l * 128;
                int k = (t + 1) * 16 + (slot >> 5), c = slot & 31;
                int row = br ? (k * NN + j) : (j * NN + k);
                pf[l] = *(const float4*)(proj + (size_t)row * PC + KVB + c * 4);
            }
        }
        #pragma unroll 2
        for (int kk = 0; kk < 16; kk++) {
            int k = t * 16 + kk;
            const u64* kp = (const u64*)&kv[kk * 128];
            u64 dh0 = 0ull, dh1 = 0ull, dh2 = 0ull, dh3 = 0ull;
            #pragma unroll
            for (int u = 0; u < 8; u++) {
                u64 kw = kp[4 * u + dq];
                fma2(dh0, q[0][u], kw); fma2(dh1, q[1][u], kw);
                fma2(dh2, q[2][u], kw); fma2(dh3, q[3][u], kw);
            }
            float p0, p1, p2, p3, xa, xb;
            up2(dh0, xa, xb); p0 = xa + xb;
            up2(dh1, xa, xb); p1 = xa + xb;
            up2(dh2, xa, xb); p2 = xa + xb;
            up2(dh3, xa, xb); p3 = xa + xb;
            p0 += __shfl_xor_sync(~0u, p0, 1); p0 += __shfl_xor_sync(~0u, p0, 2);
            p1 += __shfl_xor_sync(~0u, p1, 1); p1 += __shfl_xor_sync(~0u, p1, 2);
            p2 += __shfl_xor_sync(~0u, p2, 1); p2 += __shfl_xor_sync(~0u, p2, 2);
            p3 += __shfl_xor_sync(~0u, p3, 1); p3 += __shfl_xor_sync(~0u, p3, 2);

            int row = br ? (k * NN + i) : (i * NN + k);
            const float* ep = proj + (size_t)row * PC + EGB;
            float4 e0 = *(const float4*)ep;
            float4 e1 = *(const float4*)(ep + 4);
            float mk = mask[row];

            float pr0 = __expf(p0 + e0.x + mk); s0 += pr0;
            float pr1 = __expf(p1 + e0.y + mk); s1 += pr1;
            float pr2 = __expf(p2 + e0.z + mk); s2 += pr2;
            float pr3 = __expf(p3 + e0.w + mk); s3 += pr3;
            float w0 = pr0 * __fdividef(1.f, 1.f + __expf(-(e1.x + mk)));
            float w1 = pr1 * __fdividef(1.f, 1.f + __expf(-(e1.y + mk)));
            float w2 = pr2 * __fdividef(1.f, 1.f + __expf(-(e1.z + mk)));
            float w3 = pr3 * __fdividef(1.f, 1.f + __expf(-(e1.w + mk)));

            const u64* vp = (const u64*)&kv[kk * 128 + 64];
            u64 w20 = pk2(w0, w0), w21 = pk2(w1, w1);
            u64 w22 = pk2(w2, w2), w23 = pk2(w3, w3);
            #pragma unroll
            for (int u = 0; u < 8; u++) {
                u64 vv = vp[4 * u + dq];
                fma2(acc[0][u], w20, vv); fma2(acc[1][u], w21, vv);
                fma2(acc[2][u], w22, vv); fma2(acc[3][u], w23, vv);
            }
        }
        __syncthreads();
    }

    float r0 = __fdividef(1.f, s0), r1 = __fdividef(1.f, s1);
    float r2 = __fdividef(1.f, s2), r3 = __fdividef(1.f, s3);
    float* op = va + (size_t)(i * NN + j) * 512 + br * 4;
    #pragma unroll
    for (int u = 0; u < 8; u++) {
        int d0 = 8 * u + 2 * dq;
        float a, b;
        up2(acc[0][u], a, b); op[d0 * 8 + 0] = a * r0; op[(d0 + 1) * 8 + 0] = b * r0;
        up2(acc[1][u], a, b); op[d0 * 8 + 1] = a * r1; op[(d0 + 1) * 8 + 1] = b * r1;
        up2(acc[2][u], a, b); op[d0 * 8 + 2] = a * r2; op[(d0 + 1) * 8 + 2] = b * r2;
        up2(acc[3][u], a, b); op[d0 * 8 + 3] = a * r3; op[(d0 + 1) * 8 + 3] = b * r3;
    }
}

// -------------------- launch -----------------------------------------------
extern "C" void kernel_launch(void* const* d_in, const int* in_sizes, int n_in,
                              void* d_out, int out_size) {
    const float* e       = (const float*)d_in[0];
    const float* mask    = (const float*)d_in[1];
    const float* ln_g    = (const float*)d_in[2];
    const float* ln_b    = (const float*)d_in[3];
    const float* Wq_in   = (const float*)d_in[4];
    const float* bq_in   = (const float*)d_in[5];
    const float* Wkv_in  = (const float*)d_in[6];
    const float* bkv_in  = (const float*)d_in[7];
    const float* Weg_in  = (const float*)d_in[8];
    const float* beg_in  = (const float*)d_in[9];
    const float* Wq_out  = (const float*)d_in[10];
    const float* bq_out  = (const float*)d_in[11];
    const float* Wkv_out = (const float*)d_in[12];
    const float* bkv_out = (const float*)d_in[13];
    const float* Weg_out = (const float*)d_in[14];
    const float* beg_out = (const float*)d_in[15];
    const float* Wo      = (const float*)d_in[16];
    const float* bo      = (const float*)d_in[17];
    float* out = (float*)d_out;

    float *p_eln, *p_proj, *p_va, *p_wcat, *p_bcat;
    cudaGetSymbolAddress((void**)&p_eln,  g_eln);
    cudaGetSymbolAddress((void**)&p_proj, g_proj);
    cudaGetSymbolAddress((void**)&p_va,   g_va);
    cudaGetSymbolAddress((void**)&p_wcat, g_wcat);
    cudaGetSymbolAddress((void**)&p_bcat, g_bcat);

    // 1. LayerNorm
    ln_kernel<<<ROWS, 256>>>(e, ln_g, ln_b);
    // 2. pack weights
    pack_kernel<<<EE, 256>>>(Wq_in, bq_in, Wkv_in, bkv_in, Weg_in, beg_in,
                             Wq_out, bq_out, Wkv_out, bkv_out, Weg_out, beg_out);
    // 3. all projections in one GEMM: [25600,256] x [256,784]
    sgemm_bias<<<dim3((PC + 127) / 128, ROWS / 128), 256>>>(p_eln, p_wcat, p_bcat, p_proj,
                                                            ROWS, PC, EE);
    // 4. fused quad-cooperative flash attention, both branches
    attn_flash<<<dim3(NN, NN / 32, 2), 128>>>(p_proj, mask, p_va);
    // 5. output projection: [25600,512] x [512,256] -> d_out
    sgemm_bias<<<dim3(256 / 128, ROWS / 128), 256>>>(p_va, Wo, bo, out,
                                                     ROWS, EE, 2 * EE);
}

// round 10
// speedup vs baseline: 1.6331x; 1.6331x over previous
#include <cuda_runtime.h>
#include <cuda_bf16.h>
#include <math.h>
#include <cstdint>

#define NN 160
#define EE 256
#define HH 4
#define DD 64
#define ROWS (NN*NN)          // 25600
#define PC 784                // packed projection cols
#define SCALE 0.125f
#define LN_EPS 1e-5f

// column offsets in packed projection (fp32 proj buffer, read by attention)
#define C_QIN   0
#define C_KIN   256
#define C_VIN   320
#define C_EGIN  384
#define C_QOUT  392
#define C_KOUT  648
#define C_VOUT  712
#define C_EGOUT 776

typedef unsigned long long u64;

// -------------------- f32x2 packed helpers (sm_10x) ------------------------
__device__ __forceinline__ void fma2(u64 &d, u64 a, u64 b) {
    asm("fma.rn.f32x2 %0, %1, %2, %3;" : "=l"(d) : "l"(a), "l"(b), "l"(d));
}
__device__ __forceinline__ u64 pk2(float x, float y) {
    u64 r;
    asm("mov.b64 %0, {%1, %2};" : "=l"(r) : "r"(__float_as_uint(x)), "r"(__float_as_uint(y)));
    return r;
}
__device__ __forceinline__ void up2(u64 a, float &x, float &y) {
    unsigned lo, hi;
    asm("mov.b64 {%0, %1}, %2;" : "=r"(lo), "=r"(hi) : "l"(a));
    x = __uint_as_float(lo); y = __uint_as_float(hi);
}

// -------------------- mma/ldmatrix/cp.async helpers (base PTX, sm_80+) ------
__device__ __forceinline__ uint32_t smem_u32(const void* p) {
    uint32_t a;
    asm("{ .reg .u64 t; cvta.to.shared.u64 t, %1; cvt.u32.u64 %0, t; }" : "=r"(a) : "l"(p));
    return a;
}
#define LDMX4(r, a) asm volatile( \
    "ldmatrix.sync.aligned.m8n8.x4.shared.b16 {%0,%1,%2,%3}, [%4];" \
    : "=r"((r)[0]), "=r"((r)[1]), "=r"((r)[2]), "=r"((r)[3]) : "r"(a))
#define LDMX2(r, a) asm volatile( \
    "ldmatrix.sync.aligned.m8n8.x2.shared.b16 {%0,%1}, [%2];" \
    : "=r"((r)[0]), "=r"((r)[1]) : "r"(a))
#define CVTTF(x) asm("cvt.rna.tf32.f32 %0, %0;" : "+r"(x))
__device__ __forceinline__ void mma_tf32(float* c, const uint32_t* a, const uint32_t* b) {
    asm volatile("mma.sync.aligned.m16n8k8.row.col.f32.tf32.tf32.f32 "
        "{%0,%1,%2,%3}, {%4,%5,%6,%7}, {%8,%9}, {%0,%1,%2,%3};"
        : "+f"(c[0]), "+f"(c[1]), "+f"(c[2]), "+f"(c[3])
        : "r"(a[0]), "r"(a[1]), "r"(a[2]), "r"(a[3]), "r"(b[0]), "r"(b[1]));
}
__device__ __forceinline__ void cpa16(uint32_t dst, const void* src) {
    asm volatile("cp.async.cg.shared.global [%0], [%1], 16;" :: "r"(dst), "l"(src));
}
#define CPA_COMMIT() asm volatile("cp.async.commit_group;" ::: "memory")

// -------------------- scratch ----------------------------------------------
__device__ float g_eln[ROWS * EE];     // LN output fp32
__device__ float g_wT1[896 * EE];      // packed W1^T (N padded to 896)
__device__ float g_bcat[896];
__device__ float g_proj[ROWS * PC];    // fp32 projections
__device__ float g_va[ROWS * 512];     // attention output fp32
__device__ float g_wT2[256 * 512];     // Wo^T

// -------------------- block reduce helper (256 threads) --------------------
__device__ __forceinline__ float block_sum256(float v) {
    __shared__ float red[8];
    __shared__ float tot;
    #pragma unroll
    for (int o = 16; o; o >>= 1) v += __shfl_xor_sync(~0u, v, o);
    int wid = threadIdx.x >> 5, lane = threadIdx.x & 31;
    if (lane == 0) red[wid] = v;
    __syncthreads();
    float s = (lane < 8) ? red[lane] : 0.f;
    #pragma unroll
    for (int o = 4; o; o >>= 1) s += __shfl_xor_sync(~0u, s, o);
    if (threadIdx.x == 0) tot = s;
    __syncthreads();
    return tot;
}

// -------------------- LayerNorm --------------------------------------------
__global__ void ln_kernel(const float* __restrict__ e,
                          const float* __restrict__ g,
                          const float* __restrict__ b) {
    int r = blockIdx.x;
    int c = threadIdx.x;
    float x = e[(size_t)r * EE + c];
    float mu = block_sum256(x) * (1.f / EE);
    float dx = x - mu;
    float var = block_sum256(dx * dx) * (1.f / EE);
    g_eln[(size_t)r * EE + c] = dx * rsqrtf(var + LN_EPS) * g[c] + b[c];
}

// -------------------- pack W1^T (fold SCALE into Q) -------------------------
__global__ void pack_w1(const float* __restrict__ Wq_in,  const float* __restrict__ bq_in,
                        const float* __restrict__ Wkv_in, const float* __restrict__ bkv_in,
                        const float* __restrict__ Weg_in, const float* __restrict__ beg_in,
                        const float* __restrict__ Wq_out, const float* __restrict__ bq_out,
                        const float* __restrict__ Wkv_out,const float* __restrict__ bkv_out,
                        const float* __restrict__ Weg_out,const float* __restrict__ beg_out) {
    int n = blockIdx.x;   // 0..895
    int k = threadIdx.x;  // 0..255
    float w = 0.f, bb = 0.f;
    if (n < 256)      { w = Wq_in [k*256 + n]        * SCALE; bb = bq_in [n]       * SCALE; }
    else if (n < 384) { w = Wkv_in[k*128 + (n-256)];          bb = bkv_in[n-256]; }
    else if (n < 392) { w = Weg_in[k*8   + (n-384)];          bb = beg_in[n-384]; }
    else if (n < 648) { w = Wq_out[k*256 + (n-392)]  * SCALE; bb = bq_out[n-392]  * SCALE; }
    else if (n < 776) { w = Wkv_out[k*128 + (n-648)];         bb = bkv_out[n-648]; }
    else if (n < 784) { w = Weg_out[k*8  + (n-776)];          bb = beg_out[n-776]; }
    g_wT1[(size_t)n * EE + k] = w;
    if (k == 0) g_bcat[n] = bb;
}

// -------------------- pack Wo^T ---------------------------------------------
__global__ void pack_w2(const float* __restrict__ Wo) {
    int n = blockIdx.x;   // 0..255
    for (int k = threadIdx.x; k < 512; k += blockDim.x)
        g_wT2[(size_t)n * 512 + k] = Wo[k * 256 + n];
}

// -------------------- tf32 tensor-core GEMM: C = A[M,K] @ Bt[N,K]^T ---------
// 128x128 tile, BK=32 fp32, 8 warps (2x4), warp tile 64x32, m16n8k8 atoms.
// SW128-swizzled smem, cp.async double buffer.
__global__ __launch_bounds__(256, 2)
void tgemm(const float* __restrict__ A, const float* __restrict__ Bt,
           const float* __restrict__ bias, float* __restrict__ C,
           int K, int NC, int Nvalid) {
    extern __shared__ __align__(1024) char dsm[];
    const int tid = threadIdx.x, lid = tid & 31, wid = tid >> 5;
    const int wr = wid >> 2, wc = wid & 3;           // 2 x 4 warps
    const int bm = blockIdx.y * 128, bn = blockIdx.x * 128;
    const uint32_t smBase = smem_u32(dsm);

    float acc[4][4][4];
    #pragma unroll
    for (int mt = 0; mt < 4; mt++)
        #pragma unroll
        for (int nt = 0; nt < 4; nt++)
            #pragma unroll
            for (int q = 0; q < 4; q++) acc[mt][nt][q] = 0.f;

    const int nck = K >> 5;

    // issue chunk ck into buffer buf
    #define ISSUE(ck, buf) do { \
        const float* Ab_ = A + (size_t)bm * K + (ck) * 32; \
        const float* Bb_ = Bt + (size_t)bn * K + (ck) * 32; \
        uint32_t aD_ = smBase + (buf) * 32768; \
        uint32_t bD_ = aD_ + 16384; \
        _Pragma("unroll") \
        for (int l_ = 0; l_ < 4; l_++) { \
            int idx_ = tid + l_ * 256; \
            int r_ = idx_ >> 3, c_ = idx_ & 7; \
            int off_ = r_ * 128 + c_ * 16; \
            off_ ^= (off_ >> 3) & 0x70; \
            cpa16(aD_ + off_, Ab_ + (size_t)r_ * K + c_ * 4); \
            cpa16(bD_ + off_, Bb_ + (size_t)r_ * K + c_ * 4); \
        } \
        CPA_COMMIT(); \
    } while (0)

    ISSUE(0, 0);
    for (int ck = 0; ck < nck; ck++) {
        const int buf = ck & 1;
        if (ck + 1 < nck) {
            ISSUE(ck + 1, buf ^ 1);
            asm volatile("cp.async.wait_group 1;" ::: "memory");
        } else {
            asm volatile("cp.async.wait_group 0;" ::: "memory");
        }
        __syncthreads();

        const uint32_t aW = smBase + buf * 32768 + (wr * 64) * 128;
        const uint32_t bW = smBase + buf * 32768 + 16384 + (wc * 32) * 128;
        #pragma unroll
        for (int ks = 0; ks < 4; ks++) {
            uint32_t afr[4][4], bfr[4][2];
            #pragma unroll
            for (int mt = 0; mt < 4; mt++) {
                int off = (mt * 16 + (lid & 15)) * 128 + (ks * 2 + (lid >> 4)) * 16;
                off ^= (off >> 3) & 0x70;
                LDMX4(afr[mt], aW + off);
            }
            #pragma unroll
            for (int nt = 0; nt < 4; nt++) {
                int off = (nt * 8 + (lid & 7)) * 128 + (ks * 2 + ((lid >> 3) & 1)) * 16;
                off ^= (off >> 3) & 0x70;
                LDMX2(bfr[nt], bW + off);
            }
            #pragma unroll
            for (int mt = 0; mt < 4; mt++) {
                CVTTF(afr[mt][0]); CVTTF(afr[mt][1]);
                CVTTF(afr[mt][2]); CVTTF(afr[mt][3]);
            }
            #pragma unroll
            for (int nt = 0; nt < 4; nt++) { CVTTF(bfr[nt][0]); CVTTF(bfr[nt][1]); }
            #pragma unroll
            for (int mt = 0; mt < 4; mt++)
                #pragma unroll
                for (int nt = 0; nt < 4; nt++)
                    mma_tf32(acc[mt][nt], afr[mt], bfr[nt]);
        }
        __syncthreads();
    }
    #undef ISSUE

    #pragma unroll
    for (int mt = 0; mt < 4; mt++) {
        int row0 = bm + wr * 64 + mt * 16 + (lid >> 2);
        #pragma unroll
        for (int nt = 0; nt < 4; nt++) {
            int col0 = bn + wc * 32 + nt * 8 + (lid & 3) * 2;
            if (col0 < Nvalid) {
                float b0 = bias[col0], b1 = bias[col0 + 1];
                C[(size_t)row0 * NC + col0]           = acc[mt][nt][0] + b0;
                C[(size_t)row0 * NC + col0 + 1]       = acc[mt][nt][1] + b1;
                C[(size_t)(row0 + 8) * NC + col0]     = acc[mt][nt][2] + b0;
                C[(size_t)(row0 + 8) * NC + col0 + 1] = acc[mt][nt][3] + b1;
            }
        }
    }
}

// -------------------- quad-cooperative flash attention ----------------------
__global__ __launch_bounds__(128, 2)
void attn_flash(const float* __restrict__ proj, const float* __restrict__ mask,
                float* __restrict__ va) {
    __shared__ float kv[16 * 128];
    const int j  = blockIdx.x;
    const int ic = blockIdx.y;
    const int br = blockIdx.z;            // 0 = in, 1 = out
    const int tid = threadIdx.x;
    const int il = tid >> 2, dq = tid & 3;
    const int i  = ic * 32 + il;
    const int KVB = br ? C_KOUT : C_KIN;
    const int QB  = br ? C_QOUT : C_QIN;
    const int EGB = br ? C_EGOUT : C_EGIN;

    u64 q[4][8];
    {
        const float* qp = proj + (size_t)(i * NN + j) * PC + QB;
        #pragma unroll
        for (int h = 0; h < 4; h++)
            #pragma unroll
            for (int u = 0; u < 8; u++) {
                int d0 = 8 * u + 2 * dq;
                q[h][u] = pk2(qp[d0 * 4 + h], qp[(d0 + 1) * 4 + h]);
            }
    }
    u64 acc[4][8];
    #pragma unroll
    for (int h = 0; h < 4; h++)
        #pragma unroll
        for (int u = 0; u < 8; u++) acc[h][u] = 0ull;
    float s0 = 0.f, s1 = 0.f, s2 = 0.f, s3 = 0.f;

    float4 pf[4];
    #pragma unroll
    for (int l = 0; l < 4; l++) {
        int slot = tid + l * 128;
        int k = slot >> 5, c = slot & 31;
        int row = br ? (k * NN + j) : (j * NN + k);
        pf[l] = *(const float4*)(proj + (size_t)row * PC + KVB + c * 4);
    }

    for (int t = 0; t < 10; t++) {
        #pragma unroll
        for (int l = 0; l < 4; l++) {
            int slot = tid + l * 128;
            *(float4*)&kv[(slot >> 5) * 128 + (slot & 31) * 4] = pf[l];
        }
        __syncthreads();
        if (t < 9) {
            #pragma unroll
            for (int l = 0; l < 4; l++) {
                int slot = tid + l * 128;
                int k = (t + 1) * 16 + (slot >> 5), c = slot & 31;
                int row = br ? (k * NN + j) : (j * NN + k);
                pf[l] = *(const float4*)(proj + (size_t)row * PC + KVB + c * 4);
            }
        }
        #pragma unroll 2
        for (int kk = 0; kk < 16; kk++) {
            int k = t * 16 + kk;
            const u64* kp = (const u64*)&kv[kk * 128];
            u64 dh0 = 0ull, dh1 = 0ull, dh2 = 0ull, dh3 = 0ull;
            #pragma unroll
            for (int u = 0; u < 8; u++) {
                u64 kw = kp[4 * u + dq];
                fma2(dh0, q[0][u], kw); fma2(dh1, q[1][u], kw);
                fma2(dh2, q[2][u], kw); fma2(dh3, q[3][u], kw);
            }
            float p0, p1, p2, p3, xa, xb;
            up2(dh0, xa, xb); p0 = xa + xb;
            up2(dh1, xa, xb); p1 = xa + xb;
            up2(dh2, xa, xb); p2 = xa + xb;
            up2(dh3, xa, xb); p3 = xa + xb;
            p0 += __shfl_xor_sync(~0u, p0, 1); p0 += __shfl_xor_sync(~0u, p0, 2);
            p1 += __shfl_xor_sync(~0u, p1, 1); p1 += __shfl_xor_sync(~0u, p1, 2);
            p2 += __shfl_xor_sync(~0u, p2, 1); p2 += __shfl_xor_sync(~0u, p2, 2);
            p3 += __shfl_xor_sync(~0u, p3, 1); p3 += __shfl_xor_sync(~0u, p3, 2);

            int row = br ? (k * NN + i) : (i * NN + k);
            const float* ep = proj + (size_t)row * PC + EGB;
            float4 e0 = *(const float4*)ep;
            float4 e1 = *(const float4*)(ep + 4);
            float mk = mask[row];

            float pr0 = __expf(p0 + e0.x + mk); s0 += pr0;
            float pr1 = __expf(p1 + e0.y + mk); s1 += pr1;
            float pr2 = __expf(p2 + e0.z + mk); s2 += pr2;
            float pr3 = __expf(p3 + e0.w + mk); s3 += pr3;
            float w0 = pr0 * __fdividef(1.f, 1.f + __expf(-(e1.x + mk)));
            float w1 = pr1 * __fdividef(1.f, 1.f + __expf(-(e1.y + mk)));
            float w2 = pr2 * __fdividef(1.f, 1.f + __expf(-(e1.z + mk)));
            float w3 = pr3 * __fdividef(1.f, 1.f + __expf(-(e1.w + mk)));

            const u64* vp = (const u64*)&kv[kk * 128 + 64];
            u64 w20 = pk2(w0, w0), w21 = pk2(w1, w1);
            u64 w22 = pk2(w2, w2), w23 = pk2(w3, w3);
            #pragma unroll
            for (int u = 0; u < 8; u++) {
                u64 vv = vp[4 * u + dq];
                fma2(acc[0][u], w20, vv); fma2(acc[1][u], w21, vv);
                fma2(acc[2][u], w22, vv); fma2(acc[3][u], w23, vv);
            }
        }
        __syncthreads();
    }

    float r0 = __fdividef(1.f, s0), r1 = __fdividef(1.f, s1);
    float r2 = __fdividef(1.f, s2), r3 = __fdividef(1.f, s3);
    float* op = va + (size_t)(i * NN + j) * 512 + br * 4;
    #pragma unroll
    for (int u = 0; u < 8; u++) {
        int d0 = 8 * u + 2 * dq;
        float a, b;
        up2(acc[0][u], a, b); op[d0 * 8 + 0] = a * r0; op[(d0 + 1) * 8 + 0] = b * r0;
        up2(acc[1][u], a, b); op[d0 * 8 + 1] = a * r1; op[(d0 + 1) * 8 + 1] = b * r1;
        up2(acc[2][u], a, b); op[d0 * 8 + 2] = a * r2; op[(d0 + 1) * 8 + 2] = b * r2;
        up2(acc[3][u], a, b); op[d0 * 8 + 3] = a * r3; op[(d0 + 1) * 8 + 3] = b * r3;
    }
}

// -------------------- launch -----------------------------------------------
extern "C" void kernel_launch(void* const* d_in, const int* in_sizes, int n_in,
                              void* d_out, int out_size) {
    const float* e       = (const float*)d_in[0];
    const float* mask    = (const float*)d_in[1];
    const float* ln_g    = (const float*)d_in[2];
    const float* ln_b    = (const float*)d_in[3];
    const float* Wq_in   = (const float*)d_in[4];
    const float* bq_in   = (const float*)d_in[5];
    const float* Wkv_in  = (const float*)d_in[6];
    const float* bkv_in  = (const float*)d_in[7];
    const float* Weg_in  = (const float*)d_in[8];
    const float* beg_in  = (const float*)d_in[9];
    const float* Wq_out  = (const float*)d_in[10];
    const float* bq_out  = (const float*)d_in[11];
    const float* Wkv_out = (const float*)d_in[12];
    const float* bkv_out = (const float*)d_in[13];
    const float* Weg_out = (const float*)d_in[14];
    const float* beg_out = (const float*)d_in[15];
    const float* Wo      = (const float*)d_in[16];
    const float* bo      = (const float*)d_in[17];
    float* out = (float*)d_out;

    float *p_eln, *p_wT1, *p_bcat, *p_proj, *p_va, *p_wT2;
    cudaGetSymbolAddress((void**)&p_eln,  g_eln);
    cudaGetSymbolAddress((void**)&p_wT1,  g_wT1);
    cudaGetSymbolAddress((void**)&p_bcat, g_bcat);
    cudaGetSymbolAddress((void**)&p_proj, g_proj);
    cudaGetSymbolAddress((void**)&p_va,   g_va);
    cudaGetSymbolAddress((void**)&p_wT2,  g_wT2);

    cudaFuncSetAttribute(tgemm, cudaFuncAttributeMaxDynamicSharedMemorySize, 65536);

    // 1. LayerNorm
    ln_kernel<<<ROWS, 256>>>(e, ln_g, ln_b);
    // 2. pack transposed weights
    pack_w1<<<896, 256>>>(Wq_in, bq_in, Wkv_in, bkv_in, Weg_in, beg_in,
                          Wq_out, bq_out, Wkv_out, bkv_out, Weg_out, beg_out);
    pack_w2<<<256, 256>>>(Wo);
    // 3. projections: tf32 tensor-core GEMM [25600,256] @ [896,256]^T
    tgemm<<<dim3(7, ROWS / 128), 256, 65536>>>(p_eln, p_wT1, p_bcat, p_proj,
                                               EE, PC, PC);
    // 4. fused quad-cooperative flash attention, both branches
    attn_flash<<<dim3(NN, NN / 32, 2), 128>>>(p_proj, mask, p_va);
    // 5. output projection: tf32 GEMM [25600,512] @ [256,512]^T -> d_out
    tgemm<<<dim3(2, ROWS / 128), 256, 65536>>>(p_va, p_wT2, bo, out,
                                               512, 256, 256);
}

// round 12
// speedup vs baseline: 1.6640x; 1.0190x over previous
#include <cuda_runtime.h>
#include <cuda_bf16.h>
#include <math.h>
#include <cstdint>

#define NN 160
#define EE 256
#define HH 4
#define DD 64
#define ROWS (NN*NN)          // 25600
#define PC 784                // packed projection cols
#define SCALE 0.125f
#define LN_EPS 1e-5f

// column offsets in packed projection (fp32 proj buffer, read by attention)
#define C_QIN   0
#define C_KIN   256
#define C_VIN   320
#define C_EGIN  384
#define C_QOUT  392
#define C_KOUT  648
#define C_VOUT  712
#define C_EGOUT 776

typedef unsigned long long u64;

// -------------------- f32x2 packed helpers (sm_10x) ------------------------
__device__ __forceinline__ void fma2(u64 &d, u64 a, u64 b) {
    asm("fma.rn.f32x2 %0, %1, %2, %3;" : "=l"(d) : "l"(a), "l"(b), "l"(d));
}
__device__ __forceinline__ u64 pk2(float x, float y) {
    u64 r;
    asm("mov.b64 %0, {%1, %2};" : "=l"(r) : "r"(__float_as_uint(x)), "r"(__float_as_uint(y)));
    return r;
}
__device__ __forceinline__ void up2(u64 a, float &x, float &y) {
    unsigned lo, hi;
    asm("mov.b64 {%0, %1}, %2;" : "=r"(lo), "=r"(hi) : "l"(a));
    x = __uint_as_float(lo); y = __uint_as_float(hi);
}
__device__ __forceinline__ float tf32r(float x) {
    uint32_t u = __float_as_uint(x);
    asm("cvt.rna.tf32.f32 %0, %0;" : "+r"(u));
    return __uint_as_float(u);
}

// -------------------- mma/ldmatrix/cp.async helpers (base PTX, sm_80+) ------
__device__ __forceinline__ uint32_t smem_u32(const void* p) {
    uint32_t a;
    asm("{ .reg .u64 t; cvta.to.shared.u64 t, %1; cvt.u32.u64 %0, t; }" : "=r"(a) : "l"(p));
    return a;
}
#define LDMX4(r, a) asm volatile( \
    "ldmatrix.sync.aligned.m8n8.x4.shared.b16 {%0,%1,%2,%3}, [%4];" \
    : "=r"((r)[0]), "=r"((r)[1]), "=r"((r)[2]), "=r"((r)[3]) : "r"(a))
#define LDMX2(r, a) asm volatile( \
    "ldmatrix.sync.aligned.m8n8.x2.shared.b16 {%0,%1}, [%2];" \
    : "=r"((r)[0]), "=r"((r)[1]) : "r"(a))
__device__ __forceinline__ void mma_tf32(float* c, const uint32_t* a, const uint32_t* b) {
    asm volatile("mma.sync.aligned.m16n8k8.row.col.f32.tf32.tf32.f32 "
        "{%0,%1,%2,%3}, {%4,%5,%6,%7}, {%8,%9}, {%0,%1,%2,%3};"
        : "+f"(c[0]), "+f"(c[1]), "+f"(c[2]), "+f"(c[3])
        : "r"(a[0]), "r"(a[1]), "r"(a[2]), "r"(a[3]), "r"(b[0]), "r"(b[1]));
}
__device__ __forceinline__ void cpa16(uint32_t dst, const void* src) {
    asm volatile("cp.async.cg.shared.global [%0], [%1], 16;" :: "r"(dst), "l"(src));
}
#define CPA_COMMIT() asm volatile("cp.async.commit_group;" ::: "memory")

// -------------------- scratch ----------------------------------------------
__device__ float g_eln[ROWS * EE];     // LN output (tf32-rounded fp32)
__device__ float g_wT1[896 * EE];      // packed W1^T (N padded to 896)
__device__ float g_bcat[896];
__device__ float g_proj[ROWS * PC];    // fp32 projections
__device__ float g_va[ROWS * 512];     // attention output (tf32-rounded)
__device__ float g_wT2[256 * 512];     // Wo^T

// -------------------- block reduce helper (256 threads) --------------------
__device__ __forceinline__ float block_sum256(float v) {
    __shared__ float red[8];
    __shared__ float tot;
    #pragma unroll
    for (int o = 16; o; o >>= 1) v += __shfl_xor_sync(~0u, v, o);
    int wid = threadIdx.x >> 5, lane = threadIdx.x & 31;
    if (lane == 0) red[wid] = v;
    __syncthreads();
    float s = (lane < 8) ? red[lane] : 0.f;
    #pragma unroll
    for (int o = 4; o; o >>= 1) s += __shfl_xor_sync(~0u, s, o);
    if (threadIdx.x == 0) tot = s;
    __syncthreads();
    return tot;
}

// -------------------- LayerNorm (tf32-rounded output) -----------------------
__global__ void ln_kernel(const float* __restrict__ e,
                          const float* __restrict__ g,
                          const float* __restrict__ b) {
    int r = blockIdx.x;
    int c = threadIdx.x;
    float x = e[(size_t)r * EE + c];
    float mu = block_sum256(x) * (1.f / EE);
    float dx = x - mu;
    float var = block_sum256(dx * dx) * (1.f / EE);
    g_eln[(size_t)r * EE + c] = tf32r(dx * rsqrtf(var + LN_EPS) * g[c] + b[c]);
}

// -------------------- pack W1^T (fold SCALE into Q), tf32-rounded -----------
__global__ void pack_w1(const float* __restrict__ Wq_in,  const float* __restrict__ bq_in,
                        const float* __restrict__ Wkv_in, const float* __restrict__ bkv_in,
                        const float* __restrict__ Weg_in, const float* __restrict__ beg_in,
                        const float* __restrict__ Wq_out, const float* __restrict__ bq_out,
                        const float* __restrict__ Wkv_out,const float* __restrict__ bkv_out,
                        const float* __restrict__ Weg_out,const float* __restrict__ beg_out) {
    int n = blockIdx.x;   // 0..895
    int k = threadIdx.x;  // 0..255
    float w = 0.f, bb = 0.f;
    if (n < 256)      { w = Wq_in [k*256 + n]        * SCALE; bb = bq_in [n]       * SCALE; }
    else if (n < 384) { w = Wkv_in[k*128 + (n-256)];          bb = bkv_in[n-256]; }
    else if (n < 392) { w = Weg_in[k*8   + (n-384)];          bb = beg_in[n-384]; }
    else if (n < 648) { w = Wq_out[k*256 + (n-392)]  * SCALE; bb = bq_out[n-392]  * SCALE; }
    else if (n < 776) { w = Wkv_out[k*128 + (n-648)];         bb = bkv_out[n-648]; }
    else if (n < 784) { w = Weg_out[k*8  + (n-776)];          bb = beg_out[n-776]; }
    g_wT1[(size_t)n * EE + k] = tf32r(w);
    if (k == 0) g_bcat[n] = bb;
}

// -------------------- pack Wo^T (tf32-rounded) -------------------------------
__global__ void pack_w2(const float* __restrict__ Wo) {
    int n = blockIdx.x;   // 0..255
    for (int k = threadIdx.x; k < 512; k += blockDim.x)
        g_wT2[(size_t)n * 512 + k] = tf32r(Wo[k * 256 + n]);
}

// -------------------- tf32 tensor-core GEMM: C = A[M,K] @ Bt[N,K]^T ---------
// 128x128 tile, BK=32 fp32, 8 warps (2x4), warp tile 64x32, m16n8k8 atoms.
// Inputs pre-rounded to tf32 -> no in-loop CVT.
__global__ __launch_bounds__(256, 2)
void tgemm(const float* __restrict__ A, const float* __restrict__ Bt,
           const float* __restrict__ bias, float* __restrict__ C,
           int K, int NC, int Nvalid) {
    extern __shared__ __align__(1024) char dsm[];
    const int tid = threadIdx.x, lid = tid & 31, wid = tid >> 5;
    const int wr = wid >> 2, wc = wid & 3;           // 2 x 4 warps
    const int bm = blockIdx.y * 128, bn = blockIdx.x * 128;
    const uint32_t smBase = smem_u32(dsm);

    float acc[4][4][4];
    #pragma unroll
    for (int mt = 0; mt < 4; mt++)
        #pragma unroll
        for (int nt = 0; nt < 4; nt++)
            #pragma unroll
            for (int q = 0; q < 4; q++) acc[mt][nt][q] = 0.f;

    const int nck = K >> 5;

    #define ISSUE(ck, buf) do { \
        const float* Ab_ = A + (size_t)bm * K + (ck) * 32; \
        const float* Bb_ = Bt + (size_t)bn * K + (ck) * 32; \
        uint32_t aD_ = smBase + (buf) * 32768; \
        uint32_t bD_ = aD_ + 16384; \
        _Pragma("unroll") \
        for (int l_ = 0; l_ < 4; l_++) { \
            int idx_ = tid + l_ * 256; \
            int r_ = idx_ >> 3, c_ = idx_ & 7; \
            int off_ = r_ * 128 + c_ * 16; \
            off_ ^= (off_ >> 3) & 0x70; \
            cpa16(aD_ + off_, Ab_ + (size_t)r_ * K + c_ * 4); \
            cpa16(bD_ + off_, Bb_ + (size_t)r_ * K + c_ * 4); \
        } \
        CPA_COMMIT(); \
    } while (0)

    ISSUE(0, 0);
    for (int ck = 0; ck < nck; ck++) {
        const int buf = ck & 1;
        if (ck + 1 < nck) {
            ISSUE(ck + 1, buf ^ 1);
            asm volatile("cp.async.wait_group 1;" ::: "memory");
        } else {
            asm volatile("cp.async.wait_group 0;" ::: "memory");
        }
        __syncthreads();

        const uint32_t aW = smBase + buf * 32768 + (wr * 64) * 128;
        const uint32_t bW = smBase + buf * 32768 + 16384 + (wc * 32) * 128;
        #pragma unroll
        for (int ks = 0; ks < 4; ks++) {
            uint32_t afr[4][4], bfr[4][2];
            #pragma unroll
            for (int mt = 0; mt < 4; mt++) {
                int off = (mt * 16 + (lid & 15)) * 128 + (ks * 2 + (lid >> 4)) * 16;
                off ^= (off >> 3) & 0x70;
                LDMX4(afr[mt], aW + off);
            }
            #pragma unroll
            for (int nt = 0; nt < 4; nt++) {
                int off = (nt * 8 + (lid & 7)) * 128 + (ks * 2 + ((lid >> 3) & 1)) * 16;
                off ^= (off >> 3) & 0x70;
                LDMX2(bfr[nt], bW + off);
            }
            #pragma unroll
            for (int mt = 0; mt < 4; mt++)
                #pragma unroll
                for (int nt = 0; nt < 4; nt++)
                    mma_tf32(acc[mt][nt], afr[mt], bfr[nt]);
        }
        __syncthreads();
    }
    #undef ISSUE

    #pragma unroll
    for (int mt = 0; mt < 4; mt++) {
        int row0 = bm + wr * 64 + mt * 16 + (lid >> 2);
        #pragma unroll
        for (int nt = 0; nt < 4; nt++) {
            int col0 = bn + wc * 32 + nt * 8 + (lid & 3) * 2;
            if (col0 < Nvalid) {
                float b0 = bias[col0], b1 = bias[col0 + 1];
                C[(size_t)row0 * NC + col0]           = acc[mt][nt][0] + b0;
                C[(size_t)row0 * NC + col0 + 1]       = acc[mt][nt][1] + b1;
                C[(size_t)(row0 + 8) * NC + col0]     = acc[mt][nt][2] + b0;
                C[(size_t)(row0 + 8) * NC + col0 + 1] = acc[mt][nt][3] + b1;
            }
        }
    }
}

// -------------------- flash attention, 256 thr, 2 heads/thread --------------
// thread: dq = tid&3 (d-quad), hg = (tid>>2)&1 (head pair), il = tid>>3 (i).
// Owns d in {16u+4dq .. 16u+4dq+3}, u=0..3, for heads {2hg, 2hg+1}.
// MUFU split across dq lanes: lane role = dq>>1 (0: exp(prob), 1: sigmoid(gate)),
// myh = dq&1; recombined with 2 shfl.xor.
__global__ __launch_bounds__(256, 2)
void attn_flash(const float* __restrict__ proj, const float* __restrict__ mask,
                float* __restrict__ va) {
    __shared__ __align__(16) float kv[16 * 128];
    const int j  = blockIdx.x;
    const int ic = blockIdx.y;
    const int br = blockIdx.z;            // 0 = in, 1 = out
    const int tid = threadIdx.x;
    const int dq = tid & 3, hg = (tid >> 2) & 1, il = tid >> 3;
    const int i  = ic * 32 + il;
    const int myh = dq & 1;               // local head this lane serves in MUFU
    const int role = dq >> 1;             // 0 = prob-exp, 1 = gate-sigmoid
    const int KVB = br ? C_KOUT : C_KIN;
    const int QB  = br ? C_QOUT : C_QIN;
    const int EGB = br ? C_EGOUT : C_EGIN;

    // Q for 2 heads (2hg, 2hg+1), d-quads of this dq
    u64 q[2][4][2];
    {
        const float* qp = proj + (size_t)(i * NN + j) * PC + QB;
        #pragma unroll
        for (int h = 0; h < 2; h++) {
            int gh = 2 * hg + h;
            #pragma unroll
            for (int u = 0; u < 4; u++) {
                int d0 = 16 * u + 4 * dq;
                q[h][u][0] = pk2(qp[d0 * 4 + gh],       qp[(d0 + 1) * 4 + gh]);
                q[h][u][1] = pk2(qp[(d0 + 2) * 4 + gh], qp[(d0 + 3) * 4 + gh]);
            }
        }
    }
    u64 acc[2][4][2];
    #pragma unroll
    for (int h = 0; h < 2; h++)
        #pragma unroll
        for (int u = 0; u < 4; u++) { acc[h][u][0] = 0ull; acc[h][u][1] = 0ull; }
    float s = 0.f;   // prob-sum for local head myh

    // prefetch chunk 0: 16 k-rows x 128 floats = 512 float4; 2 per thread
    float4 pf[2];
    #pragma unroll
    for (int l = 0; l < 2; l++) {
        int slot = tid + l * 256;
        int k = slot >> 5, c = slot & 31;
        int row = br ? (k * NN + j) : (j * NN + k);
        pf[l] = *(const float4*)(proj + (size_t)row * PC + KVB + c * 4);
    }

    for (int t = 0; t < 10; t++) {
        #pragma unroll
        for (int l = 0; l < 2; l++) {
            int slot = tid + l * 256;
            *(float4*)&kv[(slot >> 5) * 128 + (slot & 31) * 4] = pf[l];
        }
        __syncthreads();
        if (t < 9) {
            #pragma unroll
            for (int l = 0; l < 2; l++) {
                int slot = tid + l * 256;
                int k = (t + 1) * 16 + (slot >> 5), c = slot & 31;
                int row = br ? (k * NN + j) : (j * NN + k);
                pf[l] = *(const float4*)(proj + (size_t)row * PC + KVB + c * 4);
            }
        }
        #pragma unroll 2
        for (int kk = 0; kk < 16; kk++) {
            int k = t * 16 + kk;
            // QK for 2 heads (4 LDS.128); u-stride = 16 floats = 4 ulonglong2
            u64 d0a = 0ull, d0b = 0ull, d1a = 0ull, d1b = 0ull;
            {
                const ulonglong2* kp = (const ulonglong2*)&kv[kk * 128 + dq * 4];
                ulonglong2 k0 = kp[0];
                ulonglong2 k1 = kp[4];
                ulonglong2 k2 = kp[8];
                ulonglong2 k3 = kp[12];
                fma2(d0a, q[0][0][0], k0.x); fma2(d0a, q[0][0][1], k0.y);
                fma2(d1a, q[1][0][0], k0.x); fma2(d1a, q[1][0][1], k0.y);
                fma2(d0b, q[0][1][0], k1.x); fma2(d0b, q[0][1][1], k1.y);
                fma2(d1b, q[1][1][0], k1.x); fma2(d1b, q[1][1][1], k1.y);
                fma2(d0a, q[0][2][0], k2.x); fma2(d0a, q[0][2][1], k2.y);
                fma2(d1a, q[1][2][0], k2.x); fma2(d1a, q[1][2][1], k2.y);
                fma2(d0b, q[0][3][0], k3.x); fma2(d0b, q[0][3][1], k3.y);
                fma2(d1b, q[1][3][0], k3.x); fma2(d1b, q[1][3][1], k3.y);
            }
            float p0, p1, xa, xb, ya, yb;
            up2(d0a, xa, xb); up2(d0b, ya, yb); p0 = (xa + xb) + (ya + yb);
            up2(d1a, xa, xb); up2(d1b, ya, yb); p1 = (xa + xb) + (ya + yb);
            p0 += __shfl_xor_sync(~0u, p0, 1); p0 += __shfl_xor_sync(~0u, p0, 2);
            p1 += __shfl_xor_sync(~0u, p1, 1); p1 += __shfl_xor_sync(~0u, p1, 2);

            // lane-role MUFU: role 0 -> exp(logit), role 1 -> sigmoid(gate)
            int row = br ? (k * NN + i) : (i * NN + k);
            float mk = mask[row];
            float eb = proj[(size_t)row * PC + EGB + (role ? 4 : 0) + 2 * hg + myh];
            float pmy = myh ? p1 : p0;
            float val = role ? -(eb + mk) : (pmy + eb + mk);
            float ex = __expf(val);
            float prg = role ? __fdividef(1.f, 1.f + ex) : ex;
            float partner = __shfl_xor_sync(~0u, prg, 2);  // pr <-> gate swap
            float w = prg * partner;                        // weight for head myh
            s += role ? partner : prg;                      // prob-sum (gate excluded)
            float wo = __shfl_xor_sync(~0u, w, 1);          // other head's weight
            float wlo = myh ? wo : w;
            float whi = myh ? w : wo;
            u64 wp0 = pk2(wlo, wlo), wp1 = pk2(whi, whi);

            // AV for 2 heads (4 LDS.128); u-stride = 4 ulonglong2
            {
                const ulonglong2* vp = (const ulonglong2*)&kv[kk * 128 + 64 + dq * 4];
                ulonglong2 v0 = vp[0];
                ulonglong2 v1 = vp[4];
                ulonglong2 v2 = vp[8];
                ulonglong2 v3 = vp[12];
                fma2(acc[0][0][0], wp0, v0.x); fma2(acc[0][0][1], wp0, v0.y);
                fma2(acc[1][0][0], wp1, v0.x); fma2(acc[1][0][1], wp1, v0.y);
                fma2(acc[0][1][0], wp0, v1.x); fma2(acc[0][1][1], wp0, v1.y);
                fma2(acc[1][1][0], wp1, v1.x); fma2(acc[1][1][1], wp1, v1.y);
                fma2(acc[0][2][0], wp0, v2.x); fma2(acc[0][2][1], wp0, v2.y);
                fma2(acc[1][2][0], wp1, v2.x); fma2(acc[1][2][1], wp1, v2.y);
                fma2(acc[0][3][0], wp0, v3.x); fma2(acc[0][3][1], wp0, v3.y);
                fma2(acc[1][3][0], wp1, v3.x); fma2(acc[1][3][1], wp1, v3.y);
            }
        }
        __syncthreads();
    }

    // gather prob-sums for both local heads
    float so = __shfl_xor_sync(~0u, s, 1);
    float s0 = myh ? so : s;
    float s1 = myh ? s : so;
    float r0 = __fdividef(1.f, s0), r1 = __fdividef(1.f, s1);

    float* op = va + (size_t)(i * NN + j) * 512 + br * 4 + 2 * hg;
    #pragma unroll
    for (int u = 0; u < 4; u++) {
        int d0 = 16 * u + 4 * dq;
        float a, b;
        up2(acc[0][u][0], a, b);
        op[d0 * 8]           = tf32r(a * r0); op[(d0 + 1) * 8]     = tf32r(b * r0);
        up2(acc[0][u][1], a, b);
        op[(d0 + 2) * 8]     = tf32r(a * r0); op[(d0 + 3) * 8]     = tf32r(b * r0);
        up2(acc[1][u][0], a, b);
        op[d0 * 8 + 1]       = tf32r(a * r1); op[(d0 + 1) * 8 + 1] = tf32r(b * r1);
        up2(acc[1][u][1], a, b);
        op[(d0 + 2) * 8 + 1] = tf32r(a * r1); op[(d0 + 3) * 8 + 1] = tf32r(b * r1);
    }
}

// -------------------- launch -----------------------------------------------
extern "C" void kernel_launch(void* const* d_in, const int* in_sizes, int n_in,
                              void* d_out, int out_size) {
    const float* e       = (const float*)d_in[0];
    const float* mask    = (const float*)d_in[1];
    const float* ln_g    = (const float*)d_in[2];
    const float* ln_b    = (const float*)d_in[3];
    const float* Wq_in   = (const float*)d_in[4];
    const float* bq_in   = (const float*)d_in[5];
    const float* Wkv_in  = (const float*)d_in[6];
    const float* bkv_in  = (const float*)d_in[7];
    const float* Weg_in  = (const float*)d_in[8];
    const float* beg_in  = (const float*)d_in[9];
    const float* Wq_out  = (const float*)d_in[10];
    const float* bq_out  = (const float*)d_in[11];
    const float* Wkv_out = (const float*)d_in[12];
    const float* bkv_out = (const float*)d_in[13];
    const float* Weg_out = (const float*)d_in[14];
    const float* beg_out = (const float*)d_in[15];
    const float* Wo      = (const float*)d_in[16];
    const float* bo      = (const float*)d_in[17];
    float* out = (float*)d_out;

    float *p_eln, *p_wT1, *p_bcat, *p_proj, *p_va, *p_wT2;
    cudaGetSymbolAddress((void**)&p_eln,  g_eln);
    cudaGetSymbolAddress((void**)&p_wT1,  g_wT1);
    cudaGetSymbolAddress((void**)&p_bcat, g_bcat);
    cudaGetSymbolAddress((void**)&p_proj, g_proj);
    cudaGetSymbolAddress((void**)&p_va,   g_va);
    cudaGetSymbolAddress((void**)&p_wT2,  g_wT2);

    cudaFuncSetAttribute(tgemm, cudaFuncAttributeMaxDynamicSharedMemorySize, 65536);

    // 1. LayerNorm (tf32-rounded out)
    ln_kernel<<<ROWS, 256>>>(e, ln_g, ln_b);
    // 2. pack transposed weights (tf32-rounded)
    pack_w1<<<896, 256>>>(Wq_in, bq_in, Wkv_in, bkv_in, Weg_in, beg_in,
                          Wq_out, bq_out, Wkv_out, bkv_out, Weg_out, beg_out);
    pack_w2<<<256, 256>>>(Wo);
    // 3. projections: tf32 tensor-core GEMM [25600,256] @ [896,256]^T
    tgemm<<<dim3(7, ROWS / 128), 256, 65536>>>(p_eln, p_wT1, p_bcat, p_proj,
                                               EE, PC, PC);
    // 4. flash attention, 2 heads/thread, lane-role MUFU split
    attn_flash<<<dim3(NN, NN / 32, 2), 256>>>(p_proj, mask, p_va);
    // 5. output projection: tf32 GEMM [25600,512] @ [256,512]^T -> d_out
    tgemm<<<dim3(2, ROWS / 128), 256, 65536>>>(p_va, p_wT2, bo, out,
                                               512, 256, 256);
}

// round 14
// speedup vs baseline: 1.8305x; 1.1000x over previous
#include <cuda_runtime.h>
#include <cuda_bf16.h>
#include <math.h>
#include <cstdint>

#define NN 160
#define EE 256
#define HH 4
#define DD 64
#define ROWS (NN*NN)          // 25600
#define PC 784                // packed projection cols
#define SCALE 0.125f
#define LN_EPS 1e-5f

// column offsets in packed projection (fp32 proj buffer, read by attention)
#define C_QIN   0
#define C_KIN   256
#define C_VIN   320
#define C_EGIN  384
#define C_QOUT  392
#define C_KOUT  648
#define C_VOUT  712
#define C_EGOUT 776

typedef unsigned long long u64;

// -------------------- f32x2 packed helpers (sm_10x) ------------------------
__device__ __forceinline__ void fma2(u64 &d, u64 a, u64 b) {
    asm("fma.rn.f32x2 %0, %1, %2, %3;" : "=l"(d) : "l"(a), "l"(b), "l"(d));
}
__device__ __forceinline__ u64 pk2(float x, float y) {
    u64 r;
    asm("mov.b64 %0, {%1, %2};" : "=l"(r) : "r"(__float_as_uint(x)), "r"(__float_as_uint(y)));
    return r;
}
__device__ __forceinline__ void up2(u64 a, float &x, float &y) {
    unsigned lo, hi;
    asm("mov.b64 {%0, %1}, %2;" : "=r"(lo), "=r"(hi) : "l"(a));
    x = __uint_as_float(lo); y = __uint_as_float(hi);
}
__device__ __forceinline__ float tf32r(float x) {
    uint32_t u = __float_as_uint(x);
    asm("cvt.rna.tf32.f32 %0, %0;" : "+r"(u));
    return __uint_as_float(u);
}

// -------------------- mma/ldmatrix/cp.async helpers (base PTX, sm_80+) ------
__device__ __forceinline__ uint32_t smem_u32(const void* p) {
    uint32_t a;
    asm("{ .reg .u64 t; cvta.to.shared.u64 t, %1; cvt.u32.u64 %0, t; }" : "=r"(a) : "l"(p));
    return a;
}
#define LDMX4(r, a) asm volatile( \
    "ldmatrix.sync.aligned.m8n8.x4.shared.b16 {%0,%1,%2,%3}, [%4];" \
    : "=r"((r)[0]), "=r"((r)[1]), "=r"((r)[2]), "=r"((r)[3]) : "r"(a))
#define LDMX2(r, a) asm volatile( \
    "ldmatrix.sync.aligned.m8n8.x2.shared.b16 {%0,%1}, [%2];" \
    : "=r"((r)[0]), "=r"((r)[1]) : "r"(a))
__device__ __forceinline__ void mma_tf32(float* c, const uint32_t* a, const uint32_t* b) {
    asm volatile("mma.sync.aligned.m16n8k8.row.col.f32.tf32.tf32.f32 "
        "{%0,%1,%2,%3}, {%4,%5,%6,%7}, {%8,%9}, {%0,%1,%2,%3};"
        : "+f"(c[0]), "+f"(c[1]), "+f"(c[2]), "+f"(c[3])
        : "r"(a[0]), "r"(a[1]), "r"(a[2]), "r"(a[3]), "r"(b[0]), "r"(b[1]));
}
__device__ __forceinline__ void cpa16(uint32_t dst, const void* src) {
    asm volatile("cp.async.cg.shared.global [%0], [%1], 16;" :: "r"(dst), "l"(src));
}
#define CPA_COMMIT() asm volatile("cp.async.commit_group;" ::: "memory")

// -------------------- scratch ----------------------------------------------
__device__ float g_eln[ROWS * EE];     // LN output (tf32-rounded fp32)
__device__ float g_wT1[896 * EE];      // packed W1^T (N padded to 896)
__device__ float g_bcat[896];
__device__ float g_proj[ROWS * PC];    // fp32 projections
__device__ float g_va[ROWS * 512];     // attention output (tf32-rounded)
__device__ float g_wT2[256 * 512];     // Wo^T
__device__ float g_egI[ROWS * 8];      // in-branch  [i][k][h][2] = pe, gate
__device__ float g_egO[ROWS * 8];      // out-branch [i][k][h][2]

// -------------------- block reduce helper (256 threads) --------------------
__device__ __forceinline__ float block_sum256(float v) {
    __shared__ float red[8];
    __shared__ float tot;
    #pragma unroll
    for (int o = 16; o; o >>= 1) v += __shfl_xor_sync(~0u, v, o);
    int wid = threadIdx.x >> 5, lane = threadIdx.x & 31;
    if (lane == 0) red[wid] = v;
    __syncthreads();
    float s = (lane < 8) ? red[lane] : 0.f;
    #pragma unroll
    for (int o = 4; o; o >>= 1) s += __shfl_xor_sync(~0u, s, o);
    if (threadIdx.x == 0) tot = s;
    __syncthreads();
    return tot;
}

// -------------------- LayerNorm (tf32-rounded output) -----------------------
__global__ void ln_kernel(const float* __restrict__ e,
                          const float* __restrict__ g,
                          const float* __restrict__ b) {
    int r = blockIdx.x;
    int c = threadIdx.x;
    float x = e[(size_t)r * EE + c];
    float mu = block_sum256(x) * (1.f / EE);
    float dx = x - mu;
    float var = block_sum256(dx * dx) * (1.f / EE);
    g_eln[(size_t)r * EE + c] = tf32r(dx * rsqrtf(var + LN_EPS) * g[c] + b[c]);
}

// -------------------- pack W1^T (fold SCALE into Q), tf32-rounded -----------
__global__ void pack_w1(const float* __restrict__ Wq_in,  const float* __restrict__ bq_in,
                        const float* __restrict__ Wkv_in, const float* __restrict__ bkv_in,
                        const float* __restrict__ Weg_in, const float* __restrict__ beg_in,
                        const float* __restrict__ Wq_out, const float* __restrict__ bq_out,
                        const float* __restrict__ Wkv_out,const float* __restrict__ bkv_out,
                        const float* __restrict__ Weg_out,const float* __restrict__ beg_out) {
    int n = blockIdx.x;   // 0..895
    int k = threadIdx.x;  // 0..255
    float w = 0.f, bb = 0.f;
    if (n < 256)      { w = Wq_in [k*256 + n]        * SCALE; bb = bq_in [n]       * SCALE; }
    else if (n < 384) { w = Wkv_in[k*128 + (n-256)];          bb = bkv_in[n-256]; }
    else if (n < 392) { w = Weg_in[k*8   + (n-384)];          bb = beg_in[n-384]; }
    else if (n < 648) { w = Wq_out[k*256 + (n-392)]  * SCALE; bb = bq_out[n-392]  * SCALE; }
    else if (n < 776) { w = Wkv_out[k*128 + (n-648)];         bb = bkv_out[n-648]; }
    else if (n < 784) { w = Weg_out[k*8  + (n-776)];          bb = beg_out[n-776]; }
    g_wT1[(size_t)n * EE + k] = tf32r(w);
    if (k == 0) g_bcat[n] = bb;
}

// -------------------- pack Wo^T (tf32-rounded) -------------------------------
__global__ void pack_w2(const float* __restrict__ Wo) {
    int n = blockIdx.x;   // 0..255
    for (int k = threadIdx.x; k < 512; k += blockDim.x)
        g_wT2[(size_t)n * 512 + k] = tf32r(Wo[k * 256 + n]);
}

// -------------------- EG -> pe/gate tables (both branches) ------------------
// Layout: eg[i][k][h][2] = { exp(E+mask), sigmoid(G+mask) }, k-contiguous.
__global__ void eg_tables(const float* __restrict__ proj, const float* __restrict__ mask) {
    int gid = blockIdx.x * 256 + threadIdx.x;     // 0..51199
    int br = gid >= ROWS;
    int rem = br ? gid - ROWS : gid;
    int i = rem / NN, k = rem % NN;
    int row = br ? (k * NN + i) : (i * NN + k);
    const float* p = proj + (size_t)row * PC + (br ? C_EGOUT : C_EGIN);
    float4 E = *(const float4*)p;
    float4 G = *(const float4*)(p + 4);
    float mk = mask[row];
    float* dst = (br ? g_egO : g_egI) + (size_t)rem * 8;
    float4 o0, o1;
    o0.x = __expf(E.x + mk); o0.y = __fdividef(1.f, 1.f + __expf(-(G.x + mk)));
    o0.z = __expf(E.y + mk); o0.w = __fdividef(1.f, 1.f + __expf(-(G.y + mk)));
    o1.x = __expf(E.z + mk); o1.y = __fdividef(1.f, 1.f + __expf(-(G.z + mk)));
    o1.z = __expf(E.w + mk); o1.w = __fdividef(1.f, 1.f + __expf(-(G.w + mk)));
    *(float4*)dst = o0;
    *(float4*)(dst + 4) = o1;
}

// -------------------- tf32 tensor-core GEMM: C = A[M,K] @ Bt[N,K]^T ---------
__global__ __launch_bounds__(256, 2)
void tgemm(const float* __restrict__ A, const float* __restrict__ Bt,
           const float* __restrict__ bias, float* __restrict__ C,
           int K, int NC, int Nvalid) {
    extern __shared__ __align__(1024) char dsm[];
    const int tid = threadIdx.x, lid = tid & 31, wid = tid >> 5;
    const int wr = wid >> 2, wc = wid & 3;           // 2 x 4 warps
    const int bm = blockIdx.y * 128, bn = blockIdx.x * 128;
    const uint32_t smBase = smem_u32(dsm);

    float acc[4][4][4];
    #pragma unroll
    for (int mt = 0; mt < 4; mt++)
        #pragma unroll
        for (int nt = 0; nt < 4; nt++)
            #pragma unroll
            for (int q = 0; q < 4; q++) acc[mt][nt][q] = 0.f;

    const int nck = K >> 5;

    #define ISSUE(ck, buf) do { \
        const float* Ab_ = A + (size_t)bm * K + (ck) * 32; \
        const float* Bb_ = Bt + (size_t)bn * K + (ck) * 32; \
        uint32_t aD_ = smBase + (buf) * 32768; \
        uint32_t bD_ = aD_ + 16384; \
        _Pragma("unroll") \
        for (int l_ = 0; l_ < 4; l_++) { \
            int idx_ = tid + l_ * 256; \
            int r_ = idx_ >> 3, c_ = idx_ & 7; \
            int off_ = r_ * 128 + c_ * 16; \
            off_ ^= (off_ >> 3) & 0x70; \
            cpa16(aD_ + off_, Ab_ + (size_t)r_ * K + c_ * 4); \
            cpa16(bD_ + off_, Bb_ + (size_t)r_ * K + c_ * 4); \
        } \
        CPA_COMMIT(); \
    } while (0)

    ISSUE(0, 0);
    for (int ck = 0; ck < nck; ck++) {
        const int buf = ck & 1;
        if (ck + 1 < nck) {
            ISSUE(ck + 1, buf ^ 1);
            asm volatile("cp.async.wait_group 1;" ::: "memory");
        } else {
            asm volatile("cp.async.wait_group 0;" ::: "memory");
        }
        __syncthreads();

        const uint32_t aW = smBase + buf * 32768 + (wr * 64) * 128;
        const uint32_t bW = smBase + buf * 32768 + 16384 + (wc * 32) * 128;
        #pragma unroll
        for (int ks = 0; ks < 4; ks++) {
            uint32_t afr[4][4], bfr[4][2];
            #pragma unroll
            for (int mt = 0; mt < 4; mt++) {
                int off = (mt * 16 + (lid & 15)) * 128 + (ks * 2 + (lid >> 4)) * 16;
                off ^= (off >> 3) & 0x70;
                LDMX4(afr[mt], aW + off);
            }
            #pragma unroll
            for (int nt = 0; nt < 4; nt++) {
                int off = (nt * 8 + (lid & 7)) * 128 + (ks * 2 + ((lid >> 3) & 1)) * 16;
                off ^= (off >> 3) & 0x70;
                LDMX2(bfr[nt], bW + off);
            }
            #pragma unroll
            for (int mt = 0; mt < 4; mt++)
                #pragma unroll
                for (int nt = 0; nt < 4; nt++)
                    mma_tf32(acc[mt][nt], afr[mt], bfr[nt]);
        }
        __syncthreads();
    }
    #undef ISSUE

    #pragma unroll
    for (int mt = 0; mt < 4; mt++) {
        int row0 = bm + wr * 64 + mt * 16 + (lid >> 2);
        #pragma unroll
        for (int nt = 0; nt < 4; nt++) {
            int col0 = bn + wc * 32 + nt * 8 + (lid & 3) * 2;
            if (col0 < Nvalid) {
                float b0 = bias[col0], b1 = bias[col0 + 1];
                C[(size_t)row0 * NC + col0]           = acc[mt][nt][0] + b0;
                C[(size_t)row0 * NC + col0 + 1]       = acc[mt][nt][1] + b1;
                C[(size_t)(row0 + 8) * NC + col0]     = acc[mt][nt][2] + b0;
                C[(size_t)(row0 + 8) * NC + col0 + 1] = acc[mt][nt][3] + b1;
            }
        }
    }
}

// -------------------- flash attention, all-smem mainloop --------------------
// smem (floats): kv[2][2048], pg[2][32*136]  (pg pitch 136 = conflict-free)
// thread: dq = tid&3, hg = (tid>>2)&1, il = tid>>3; myh = dq&1.
#define PGP 136
#define SM_PG 4096
#define SM_FLOATS (4096 + 2 * 32 * PGP)   // 12800 floats = 51200 B

__global__ __launch_bounds__(256, 2)
void attn_flash(const float* __restrict__ proj, const float* __restrict__ egI,
                const float* __restrict__ egO, float* __restrict__ va) {
    extern __shared__ __align__(16) float sm[];
    const int j  = blockIdx.x;
    const int ic = blockIdx.y;
    const int br = blockIdx.z;            // 0 = in, 1 = out
    const int tid = threadIdx.x;
    const int dq = tid & 3, hg = (tid >> 2) & 1, il = tid >> 3;
    const int i  = ic * 32 + il;
    const int myh = dq & 1;
    const int KVB = br ? C_KOUT : C_KIN;
    const int QB  = br ? C_QOUT : C_QIN;
    const float* eg = br ? egO : egI;
    const uint32_t smB = smem_u32(sm);

    // Q for 2 heads (2hg, 2hg+1), d-quads of this dq
    u64 q[2][4][2];
    {
        const float* qp = proj + (size_t)(i * NN + j) * PC + QB;
        #pragma unroll
        for (int h = 0; h < 2; h++) {
            int gh = 2 * hg + h;
            #pragma unroll
            for (int u = 0; u < 4; u++) {
                int d0 = 16 * u + 4 * dq;
                q[h][u][0] = pk2(qp[d0 * 4 + gh],       qp[(d0 + 1) * 4 + gh]);
                q[h][u][1] = pk2(qp[(d0 + 2) * 4 + gh], qp[(d0 + 3) * 4 + gh]);
            }
        }
    }
    u64 acc[2][4][2];
    #pragma unroll
    for (int h = 0; h < 2; h++)
        #pragma unroll
        for (int u = 0; u < 4; u++) { acc[h][u][0] = 0ull; acc[h][u][1] = 0ull; }
    float s = 0.f;   // prob-sum for local head myh

    // stage tile t into buffer buf: kv (512 x 16B) + pe/gate (1024 x 16B)
    #define ISSUE_T(t, buf) do { \
        _Pragma("unroll") \
        for (int l_ = 0; l_ < 2; l_++) { \
            int slot_ = tid + l_ * 256; \
            int kr_ = slot_ >> 5, c_ = slot_ & 31; \
            int k_ = (t) * 16 + kr_; \
            int row_ = br ? (k_ * NN + j) : (j * NN + k_); \
            cpa16(smB + ((buf) * 2048 + kr_ * 128 + c_ * 4) * 4, \
                  proj + (size_t)row_ * PC + KVB + c_ * 4); \
        } \
        _Pragma("unroll") \
        for (int l_ = 0; l_ < 4; l_++) { \
            int idx_ = tid + l_ * 256; \
            int iL_ = idx_ >> 5, seg_ = idx_ & 31; \
            cpa16(smB + (SM_PG + (buf) * 32 * PGP + iL_ * PGP + seg_ * 4) * 4, \
                  eg + ((size_t)(ic * 32 + iL_) * NN + (t) * 16) * 8 + seg_ * 4); \
        } \
        CPA_COMMIT(); \
    } while (0)

    ISSUE_T(0, 0);
    for (int t = 0; t < 10; t++) {
        const int buf = t & 1;
        if (t < 9) {
            ISSUE_T(t + 1, buf ^ 1);
            asm volatile("cp.async.wait_group 1;" ::: "memory");
        } else {
            asm volatile("cp.async.wait_group 0;" ::: "memory");
        }
        __syncthreads();

        const float* kvb = sm + buf * 2048;
        const float* pgb = sm + SM_PG + buf * 32 * PGP + il * PGP + (2 * hg + myh) * 2;
        #pragma unroll 2
        for (int kk = 0; kk < 16; kk++) {
            // QK for 2 heads (4 LDS.128); u-stride = 16 floats = 4 ulonglong2
            u64 d0a = 0ull, d0b = 0ull, d1a = 0ull, d1b = 0ull;
            {
                const ulonglong2* kp = (const ulonglong2*)&kvb[kk * 128 + dq * 4];
                ulonglong2 k0 = kp[0];
                ulonglong2 k1 = kp[4];
                ulonglong2 k2 = kp[8];
                ulonglong2 k3 = kp[12];
                fma2(d0a, q[0][0][0], k0.x); fma2(d0a, q[0][0][1], k0.y);
                fma2(d1a, q[1][0][0], k0.x); fma2(d1a, q[1][0][1], k0.y);
                fma2(d0b, q[0][1][0], k1.x); fma2(d0b, q[0][1][1], k1.y);
                fma2(d1b, q[1][1][0], k1.x); fma2(d1b, q[1][1][1], k1.y);
                fma2(d0a, q[0][2][0], k2.x); fma2(d0a, q[0][2][1], k2.y);
                fma2(d1a, q[1][2][0], k2.x); fma2(d1a, q[1][2][1], k2.y);
                fma2(d0b, q[0][3][0], k3.x); fma2(d0b, q[0][3][1], k3.y);
                fma2(d1b, q[1][3][0], k3.x); fma2(d1b, q[1][3][1], k3.y);
            }
            float p0, p1, xa, xb, ya, yb;
            up2(d0a, xa, xb); up2(d0b, ya, yb); p0 = (xa + xb) + (ya + yb);
            up2(d1a, xa, xb); up2(d1b, ya, yb); p1 = (xa + xb) + (ya + yb);
            p0 += __shfl_xor_sync(~0u, p0, 1); p0 += __shfl_xor_sync(~0u, p0, 2);
            p1 += __shfl_xor_sync(~0u, p1, 1); p1 += __shfl_xor_sync(~0u, p1, 2);

            // pe/gate from smem; 1 exp per lane (head myh), recombine via shfl
            float2 pg = *(const float2*)&pgb[kk * 8];
            float ex = __expf(myh ? p1 : p0);
            float pr = ex * pg.x;           // exp(logit) * exp(E+mk)
            s += pr;
            float w = pr * pg.y;            // * gate
            float wo = __shfl_xor_sync(~0u, w, 1);
            float wlo = myh ? wo : w;
            float whi = myh ? w : wo;
            u64 wp0 = pk2(wlo, wlo), wp1 = pk2(whi, whi);

            // AV for 2 heads (4 LDS.128)
            {
                const ulonglong2* vp = (const ulonglong2*)&kvb[kk * 128 + 64 + dq * 4];
                ulonglong2 v0 = vp[0];
                ulonglong2 v1 = vp[4];
                ulonglong2 v2 = vp[8];
                ulonglong2 v3 = vp[12];
                fma2(acc[0][0][0], wp0, v0.x); fma2(acc[0][0][1], wp0, v0.y);
                fma2(acc[1][0][0], wp1, v0.x); fma2(acc[1][0][1], wp1, v0.y);
                fma2(acc[0][1][0], wp0, v1.x); fma2(acc[0][1][1], wp0, v1.y);
                fma2(acc[1][1][0], wp1, v1.x); fma2(acc[1][1][1], wp1, v1.y);
                fma2(acc[0][2][0], wp0, v2.x); fma2(acc[0][2][1], wp0, v2.y);
                fma2(acc[1][2][0], wp1, v2.x); fma2(acc[1][2][1], wp1, v2.y);
                fma2(acc[0][3][0], wp0, v3.x); fma2(acc[0][3][1], wp0, v3.y);
                fma2(acc[1][3][0], wp1, v3.x); fma2(acc[1][3][1], wp1, v3.y);
            }
        }
        __syncthreads();
    }
    #undef ISSUE_T

    // gather prob-sums for both local heads
    float so = __shfl_xor_sync(~0u, s, 1);
    float s0 = myh ? so : s;
    float s1 = myh ? s : so;
    float r0 = __fdividef(1.f, s0), r1 = __fdividef(1.f, s1);

    float* op = va + (size_t)(i * NN + j) * 512 + br * 4 + 2 * hg;
    #pragma unroll
    for (int u = 0; u < 4; u++) {
        int d0 = 16 * u + 4 * dq;
        float a, b;
        up2(acc[0][u][0], a, b);
        op[d0 * 8]           = tf32r(a * r0); op[(d0 + 1) * 8]     = tf32r(b * r0);
        up2(acc[0][u][1], a, b);
        op[(d0 + 2) * 8]     = tf32r(a * r0); op[(d0 + 3) * 8]     = tf32r(b * r0);
        up2(acc[1][u][0], a, b);
        op[d0 * 8 + 1]       = tf32r(a * r1); op[(d0 + 1) * 8 + 1] = tf32r(b * r1);
        up2(acc[1][u][1], a, b);
        op[(d0 + 2) * 8 + 1] = tf32r(a * r1); op[(d0 + 3) * 8 + 1] = tf32r(b * r1);
    }
}

// -------------------- launch -----------------------------------------------
extern "C" void kernel_launch(void* const* d_in, const int* in_sizes, int n_in,
                              void* d_out, int out_size) {
    const float* e       = (const float*)d_in[0];
    const float* mask    = (const float*)d_in[1];
    const float* ln_g    = (const float*)d_in[2];
    const float* ln_b    = (const float*)d_in[3];
    const float* Wq_in   = (const float*)d_in[4];
    const float* bq_in   = (const float*)d_in[5];
    const float* Wkv_in  = (const float*)d_in[6];
    const float* bkv_in  = (const float*)d_in[7];
    const float* Weg_in  = (const float*)d_in[8];
    const float* beg_in  = (const float*)d_in[9];
    const float* Wq_out  = (const float*)d_in[10];
    const float* bq_out  = (const float*)d_in[11];
    const float* Wkv_out = (const float*)d_in[12];
    const float* bkv_out = (const float*)d_in[13];
    const float* Weg_out = (const float*)d_in[14];
    const float* beg_out = (const float*)d_in[15];
    const float* Wo      = (const float*)d_in[16];
    const float* bo      = (const float*)d_in[17];
    float* out = (float*)d_out;

    float *p_eln, *p_wT1, *p_bcat, *p_proj, *p_va, *p_wT2, *p_egI, *p_egO;
    cudaGetSymbolAddress((void**)&p_eln,  g_eln);
    cudaGetSymbolAddress((void**)&p_wT1,  g_wT1);
    cudaGetSymbolAddress((void**)&p_bcat, g_bcat);
    cudaGetSymbolAddress((void**)&p_proj, g_proj);
    cudaGetSymbolAddress((void**)&p_va,   g_va);
    cudaGetSymbolAddress((void**)&p_wT2,  g_wT2);
    cudaGetSymbolAddress((void**)&p_egI,  g_egI);
    cudaGetSymbolAddress((void**)&p_egO,  g_egO);

    cudaFuncSetAttribute(tgemm, cudaFuncAttributeMaxDynamicSharedMemorySize, 65536);
    cudaFuncSetAttribute(attn_flash, cudaFuncAttributeMaxDynamicSharedMemorySize,
                         SM_FLOATS * 4);

    // 1. LayerNorm (tf32-rounded out)
    ln_kernel<<<ROWS, 256>>>(e, ln_g, ln_b);
    // 2. pack transposed weights (tf32-rounded)
    pack_w1<<<896, 256>>>(Wq_in, bq_in, Wkv_in, bkv_in, Weg_in, beg_in,
                          Wq_out, bq_out, Wkv_out, bkv_out, Weg_out, beg_out);
    pack_w2<<<256, 256>>>(Wo);
    // 3. projections: tf32 tensor-core GEMM [25600,256] @ [896,256]^T
    tgemm<<<dim3(7, ROWS / 128), 256, 65536>>>(p_eln, p_wT1, p_bcat, p_proj,
                                               EE, PC, PC);
    // 4a. precompute pe/gate tables (folds mask, exp, sigmoid)
    eg_tables<<<2 * ROWS / 256, 256>>>(p_proj, mask);
    // 4b. flash attention, all-smem mainloop
    attn_flash<<<dim3(NN, NN / 32, 2), 256, SM_FLOATS * 4>>>(p_proj, p_egI, p_egO, p_va);
    // 5. output projection: tf32 GEMM [25600,512] @ [256,512]^T -> d_out
    tgemm<<<dim3(2, ROWS / 128), 256, 65536>>>(p_va, p_wT2, bo, out,
                                               512, 256, 256);
}

// round 15
// speedup vs baseline: 1.9202x; 1.0490x over previous
#include <cuda_runtime.h>
#include <cuda_bf16.h>
#include <math.h>
#include <cstdint>

#define NN 160
#define EE 256
#define HH 4
#define DD 64
#define ROWS (NN*NN)          // 25600
#define PC 784                // packed projection cols
#define SCALE 0.125f
#define LN_EPS 1e-5f

// column offsets in packed projection (fp32 proj buffer, read by attention)
#define C_QIN   0
#define C_KIN   256
#define C_VIN   320
#define C_EGIN  384
#define C_QOUT  392
#define C_KOUT  648
#define C_VOUT  712
#define C_EGOUT 776

typedef unsigned long long u64;

// -------------------- f32x2 packed helpers (sm_10x) ------------------------
__device__ __forceinline__ void fma2(u64 &d, u64 a, u64 b) {
    asm("fma.rn.f32x2 %0, %1, %2, %3;" : "=l"(d) : "l"(a), "l"(b), "l"(d));
}
__device__ __forceinline__ u64 pk2(float x, float y) {
    u64 r;
    asm("mov.b64 %0, {%1, %2};" : "=l"(r) : "r"(__float_as_uint(x)), "r"(__float_as_uint(y)));
    return r;
}
__device__ __forceinline__ void up2(u64 a, float &x, float &y) {
    unsigned lo, hi;
    asm("mov.b64 {%0, %1}, %2;" : "=r"(lo), "=r"(hi) : "l"(a));
    x = __uint_as_float(lo); y = __uint_as_float(hi);
}
__device__ __forceinline__ float tf32r(float x) {
    uint32_t u = __float_as_uint(x);
    asm("cvt.rna.tf32.f32 %0, %0;" : "+r"(u));
    return __uint_as_float(u);
}

// -------------------- mma/ldmatrix/cp.async helpers (base PTX, sm_80+) ------
__device__ __forceinline__ uint32_t smem_u32(const void* p) {
    uint32_t a;
    asm("{ .reg .u64 t; cvta.to.shared.u64 t, %1; cvt.u32.u64 %0, t; }" : "=r"(a) : "l"(p));
    return a;
}
#define LDMX4(r, a) asm volatile( \
    "ldmatrix.sync.aligned.m8n8.x4.shared.b16 {%0,%1,%2,%3}, [%4];" \
    : "=r"((r)[0]), "=r"((r)[1]), "=r"((r)[2]), "=r"((r)[3]) : "r"(a))
#define LDMX2(r, a) asm volatile( \
    "ldmatrix.sync.aligned.m8n8.x2.shared.b16 {%0,%1}, [%2];" \
    : "=r"((r)[0]), "=r"((r)[1]) : "r"(a))
__device__ __forceinline__ void mma_tf32(float* c, const uint32_t* a, const uint32_t* b) {
    asm volatile("mma.sync.aligned.m16n8k8.row.col.f32.tf32.tf32.f32 "
        "{%0,%1,%2,%3}, {%4,%5,%6,%7}, {%8,%9}, {%0,%1,%2,%3};"
        : "+f"(c[0]), "+f"(c[1]), "+f"(c[2]), "+f"(c[3])
        : "r"(a[0]), "r"(a[1]), "r"(a[2]), "r"(a[3]), "r"(b[0]), "r"(b[1]));
}
__device__ __forceinline__ void cpa16(uint32_t dst, const void* src) {
    asm volatile("cp.async.cg.shared.global [%0], [%1], 16;" :: "r"(dst), "l"(src));
}
#define CPA_COMMIT() asm volatile("cp.async.commit_group;" ::: "memory")

// -------------------- scratch ----------------------------------------------
__device__ float g_eln[ROWS * EE];     // LN output (tf32-rounded fp32)
__device__ float g_wT1[896 * EE];      // packed W1^T (N padded to 896)
__device__ float g_bcat[896];
__device__ float g_proj[ROWS * PC];    // fp32 projections
__device__ float g_va[ROWS * 512];     // attention output (tf32-rounded)
__device__ float g_wT2[256 * 512];     // Wo^T
__device__ float g_egI[ROWS * 8];      // in-branch  [i][k][h][2] = pe, gate
__device__ float g_egO[ROWS * 8];      // out-branch [i][k][h][2]

// -------------------- LayerNorm: warp per row (no block barriers) -----------
__global__ __launch_bounds__(256)
void ln_kernel(const float* __restrict__ e,
               const float* __restrict__ g,
               const float* __restrict__ b) {
    int wid = threadIdx.x >> 5, lane = threadIdx.x & 31;
    int r = blockIdx.x * 8 + wid;
    const float* er = e + (size_t)r * EE;
    float4 v0 = *(const float4*)(er + lane * 8);
    float4 v1 = *(const float4*)(er + lane * 8 + 4);
    float su = v0.x + v0.y + v0.z + v0.w + v1.x + v1.y + v1.z + v1.w;
    #pragma unroll
    for (int o = 16; o; o >>= 1) su += __shfl_xor_sync(~0u, su, o);
    float mu = su * (1.f / EE);
    float d0 = v0.x - mu, d1 = v0.y - mu, d2 = v0.z - mu, d3 = v0.w - mu;
    float d4 = v1.x - mu, d5 = v1.y - mu, d6 = v1.z - mu, d7 = v1.w - mu;
    float sq = d0*d0 + d1*d1 + d2*d2 + d3*d3 + d4*d4 + d5*d5 + d6*d6 + d7*d7;
    #pragma unroll
    for (int o = 16; o; o >>= 1) sq += __shfl_xor_sync(~0u, sq, o);
    float rs = rsqrtf(sq * (1.f / EE) + LN_EPS);
    float* orow = g_eln + (size_t)r * EE + lane * 8;
    const float* gp = g + lane * 8;
    const float* bp = b + lane * 8;
    float4 ga = *(const float4*)gp, gb2 = *(const float4*)(gp + 4);
    float4 ba = *(const float4*)bp, bb2 = *(const float4*)(bp + 4);
    float4 o0, o1;
    o0.x = tf32r(d0 * rs * ga.x + ba.x); o0.y = tf32r(d1 * rs * ga.y + ba.y);
    o0.z = tf32r(d2 * rs * ga.z + ba.z); o0.w = tf32r(d3 * rs * ga.w + ba.w);
    o1.x = tf32r(d4 * rs * gb2.x + bb2.x); o1.y = tf32r(d5 * rs * gb2.y + bb2.y);
    o1.z = tf32r(d6 * rs * gb2.z + bb2.z); o1.w = tf32r(d7 * rs * gb2.w + bb2.w);
    *(float4*)orow = o0;
    *(float4*)(orow + 4) = o1;
}

// -------------------- pack W1^T + Wo^T (one launch), tf32-rounded -----------
__global__ void pack_w(const float* __restrict__ Wq_in,  const float* __restrict__ bq_in,
                       const float* __restrict__ Wkv_in, const float* __restrict__ bkv_in,
                       const float* __restrict__ Weg_in, const float* __restrict__ beg_in,
                       const float* __restrict__ Wq_out, const float* __restrict__ bq_out,
                       const float* __restrict__ Wkv_out,const float* __restrict__ bkv_out,
                       const float* __restrict__ Weg_out,const float* __restrict__ beg_out,
                       const float* __restrict__ Wo) {
    int n = blockIdx.x;
    int k = threadIdx.x;
    if (n < 896) {
        float w = 0.f, bb = 0.f;
        if (n < 256)      { w = Wq_in [k*256 + n]        * SCALE; bb = bq_in [n]       * SCALE; }
        else if (n < 384) { w = Wkv_in[k*128 + (n-256)];          bb = bkv_in[n-256]; }
        else if (n < 392) { w = Weg_in[k*8   + (n-384)];          bb = beg_in[n-384]; }
        else if (n < 648) { w = Wq_out[k*256 + (n-392)]  * SCALE; bb = bq_out[n-392]  * SCALE; }
        else if (n < 776) { w = Wkv_out[k*128 + (n-648)];         bb = bkv_out[n-648]; }
        else if (n < 784) { w = Weg_out[k*8  + (n-776)];          bb = beg_out[n-776]; }
        g_wT1[(size_t)n * EE + k] = tf32r(w);
        if (k == 0) g_bcat[n] = bb;
    } else {
        int n2 = n - 896;   // 0..255
        g_wT2[(size_t)n2 * 512 + k]       = tf32r(Wo[k * 256 + n2]);
        g_wT2[(size_t)n2 * 512 + 256 + k] = tf32r(Wo[(256 + k) * 256 + n2]);
    }
}

// -------------------- EG -> pe/gate tables (both branches) ------------------
__global__ void eg_tables(const float* __restrict__ proj, const float* __restrict__ mask) {
    int gid = blockIdx.x * 256 + threadIdx.x;     // 0..51199
    int br = gid >= ROWS;
    int rem = br ? gid - ROWS : gid;
    int i = rem / NN, k = rem % NN;
    int row = br ? (k * NN + i) : (i * NN + k);
    const float* p = proj + (size_t)row * PC + (br ? C_EGOUT : C_EGIN);
    float4 E = *(const float4*)p;
    float4 G = *(const float4*)(p + 4);
    float mk = mask[row];
    float* dst = (br ? g_egO : g_egI) + (size_t)rem * 8;
    float4 o0, o1;
    o0.x = __expf(E.x + mk); o0.y = __fdividef(1.f, 1.f + __expf(-(G.x + mk)));
    o0.z = __expf(E.y + mk); o0.w = __fdividef(1.f, 1.f + __expf(-(G.y + mk)));
    o1.x = __expf(E.z + mk); o1.y = __fdividef(1.f, 1.f + __expf(-(G.z + mk)));
    o1.z = __expf(E.w + mk); o1.w = __fdividef(1.f, 1.f + __expf(-(G.w + mk)));
    *(float4*)dst = o0;
    *(float4*)(dst + 4) = o1;
}

// -------------------- tf32 tensor-core GEMM: C = A[M,K] @ Bt[N,K]^T ---------
__global__ __launch_bounds__(256, 2)
void tgemm(const float* __restrict__ A, const float* __restrict__ Bt,
           const float* __restrict__ bias, float* __restrict__ C,
           int K, int NC, int Nvalid) {
    extern __shared__ __align__(1024) char dsm[];
    const int tid = threadIdx.x, lid = tid & 31, wid = tid >> 5;
    const int wr = wid >> 2, wc = wid & 3;           // 2 x 4 warps
    const int bm = blockIdx.y * 128, bn = blockIdx.x * 128;
    const uint32_t smBase = smem_u32(dsm);

    float acc[4][4][4];
    #pragma unroll
    for (int mt = 0; mt < 4; mt++)
        #pragma unroll
        for (int nt = 0; nt < 4; nt++)
            #pragma unroll
            for (int q = 0; q < 4; q++) acc[mt][nt][q] = 0.f;

    const int nck = K >> 5;

    #define ISSUE(ck, buf) do { \
        const float* Ab_ = A + (size_t)bm * K + (ck) * 32; \
        const float* Bb_ = Bt + (size_t)bn * K + (ck) * 32; \
        uint32_t aD_ = smBase + (buf) * 32768; \
        uint32_t bD_ = aD_ + 16384; \
        _Pragma("unroll") \
        for (int l_ = 0; l_ < 4; l_++) { \
            int idx_ = tid + l_ * 256; \
            int r_ = idx_ >> 3, c_ = idx_ & 7; \
            int off_ = r_ * 128 + c_ * 16; \
            off_ ^= (off_ >> 3) & 0x70; \
            cpa16(aD_ + off_, Ab_ + (size_t)r_ * K + c_ * 4); \
            cpa16(bD_ + off_, Bb_ + (size_t)r_ * K + c_ * 4); \
        } \
        CPA_COMMIT(); \
    } while (0)

    ISSUE(0, 0);
    for (int ck = 0; ck < nck; ck++) {
        const int buf = ck & 1;
        if (ck + 1 < nck) {
            ISSUE(ck + 1, buf ^ 1);
            asm volatile("cp.async.wait_group 1;" ::: "memory");
        } else {
            asm volatile("cp.async.wait_group 0;" ::: "memory");
        }
        __syncthreads();

        const uint32_t aW = smBase + buf * 32768 + (wr * 64) * 128;
        const uint32_t bW = smBase + buf * 32768 + 16384 + (wc * 32) * 128;
        #pragma unroll
        for (int ks = 0; ks < 4; ks++) {
            uint32_t afr[4][4], bfr[4][2];
            #pragma unroll
            for (int mt = 0; mt < 4; mt++) {
                int off = (mt * 16 + (lid & 15)) * 128 + (ks * 2 + (lid >> 4)) * 16;
                off ^= (off >> 3) & 0x70;
                LDMX4(afr[mt], aW + off);
            }
            #pragma unroll
            for (int nt = 0; nt < 4; nt++) {
                int off = (nt * 8 + (lid & 7)) * 128 + (ks * 2 + ((lid >> 3) & 1)) * 16;
                off ^= (off >> 3) & 0x70;
                LDMX2(bfr[nt], bW + off);
            }
            #pragma unroll
            for (int mt = 0; mt < 4; mt++)
                #pragma unroll
                for (int nt = 0; nt < 4; nt++)
                    mma_tf32(acc[mt][nt], afr[mt], bfr[nt]);
        }
        __syncthreads();
    }
    #undef ISSUE

    #pragma unroll
    for (int mt = 0; mt < 4; mt++) {
        int row0 = bm + wr * 64 + mt * 16 + (lid >> 2);
        #pragma unroll
        for (int nt = 0; nt < 4; nt++) {
            int col0 = bn + wc * 32 + nt * 8 + (lid & 3) * 2;
            if (col0 < Nvalid) {
                float b0 = bias[col0], b1 = bias[col0 + 1];
                C[(size_t)row0 * NC + col0]           = acc[mt][nt][0] + b0;
                C[(size_t)row0 * NC + col0 + 1]       = acc[mt][nt][1] + b1;
                C[(size_t)(row0 + 8) * NC + col0]     = acc[mt][nt][2] + b0;
                C[(size_t)(row0 + 8) * NC + col0 + 1] = acc[mt][nt][3] + b1;
            }
        }
    }
}

// -------------------- flash attention, phase-split mainloop -----------------
// smem (floats): kv[2][2048], pg[2][32*136]
// thread: dq = tid&3, hg = (tid>>2)&1, il = tid>>3; myh = dq&1.
// Phase A: 8 k's of QK + 2-shfl role-swap reduction -> pm[8]
// Phase B: 8 independent exp*pe, gate -> w[8], s
// Phase C: 8 k's of AV (w-exchange shfl pipelined)
#define PGP 136
#define SM_PG 4096
#define SM_FLOATS (4096 + 2 * 32 * PGP)   // 12800 floats = 51200 B

__global__ __launch_bounds__(256, 2)
void attn_flash(const float* __restrict__ proj, const float* __restrict__ egI,
                const float* __restrict__ egO, float* __restrict__ va) {
    extern __shared__ __align__(16) float sm[];
    const int j  = blockIdx.x;
    const int ic = blockIdx.y;
    const int br = blockIdx.z;            // 0 = in, 1 = out
    const int tid = threadIdx.x;
    const int dq = tid & 3, hg = (tid >> 2) & 1, il = tid >> 3;
    const int i  = ic * 32 + il;
    const int myh = dq & 1;
    const int KVB = br ? C_KOUT : C_KIN;
    const int QB  = br ? C_QOUT : C_QIN;
    const float* eg = br ? egO : egI;
    const uint32_t smB = smem_u32(sm);

    // Q for 2 heads (2hg, 2hg+1), d-quads of this dq
    u64 q[2][4][2];
    {
        const float* qp = proj + (size_t)(i * NN + j) * PC + QB;
        #pragma unroll
        for (int h = 0; h < 2; h++) {
            int gh = 2 * hg + h;
            #pragma unroll
            for (int u = 0; u < 4; u++) {
                int d0 = 16 * u + 4 * dq;
                q[h][u][0] = pk2(qp[d0 * 4 + gh],       qp[(d0 + 1) * 4 + gh]);
                q[h][u][1] = pk2(qp[(d0 + 2) * 4 + gh], qp[(d0 + 3) * 4 + gh]);
            }
        }
    }
    u64 acc[2][4][2];
    #pragma unroll
    for (int h = 0; h < 2; h++)
        #pragma unroll
        for (int u = 0; u < 4; u++) { acc[h][u][0] = 0ull; acc[h][u][1] = 0ull; }
    float s = 0.f;   // prob-sum for local head myh

    #define ISSUE_T(t, buf) do { \
        _Pragma("unroll") \
        for (int l_ = 0; l_ < 2; l_++) { \
            int slot_ = tid + l_ * 256; \
            int kr_ = slot_ >> 5, c_ = slot_ & 31; \
            int k_ = (t) * 16 + kr_; \
            int row_ = br ? (k_ * NN + j) : (j * NN + k_); \
            cpa16(smB + ((buf) * 2048 + kr_ * 128 + c_ * 4) * 4, \
                  proj + (size_t)row_ * PC + KVB + c_ * 4); \
        } \
        _Pragma("unroll") \
        for (int l_ = 0; l_ < 4; l_++) { \
            int idx_ = tid + l_ * 256; \
            int iL_ = idx_ >> 5, seg_ = idx_ & 31; \
            cpa16(smB + (SM_PG + (buf) * 32 * PGP + iL_ * PGP + seg_ * 4) * 4, \
                  eg + ((size_t)(ic * 32 + iL_) * NN + (t) * 16) * 8 + seg_ * 4); \
        } \
        CPA_COMMIT(); \
    } while (0)

    ISSUE_T(0, 0);
    for (int t = 0; t < 10; t++) {
        const int buf = t & 1;
        if (t < 9) {
            ISSUE_T(t + 1, buf ^ 1);
            asm volatile("cp.async.wait_group 1;" ::: "memory");
        } else {
            asm volatile("cp.async.wait_group 0;" ::: "memory");
        }
        __syncthreads();

        const float* kvb = sm + buf * 2048;
        const float* pgb = sm + SM_PG + buf * 32 * PGP + il * PGP + (2 * hg + myh) * 2;
        #pragma unroll
        for (int kb = 0; kb < 2; kb++) {
            // -------- Phase A: QK dots + role-swap reduction --------
            float pm[8];
            #pragma unroll
            for (int kk = 0; kk < 8; kk++) {
                const int kkk = kb * 8 + kk;
                u64 d0a = 0ull, d0b = 0ull, d1a = 0ull, d1b = 0ull;
                const ulonglong2* kp = (const ulonglong2*)&kvb[kkk * 128 + dq * 4];
                ulonglong2 k0 = kp[0];
                ulonglong2 k1 = kp[4];
                ulonglong2 k2 = kp[8];
                ulonglong2 k3 = kp[12];
                fma2(d0a, q[0][0][0], k0.x); fma2(d0a, q[0][0][1], k0.y);
                fma2(d1a, q[1][0][0], k0.x); fma2(d1a, q[1][0][1], k0.y);
                fma2(d0b, q[0][1][0], k1.x); fma2(d0b, q[0][1][1], k1.y);
                fma2(d1b, q[1][1][0], k1.x); fma2(d1b, q[1][1][1], k1.y);
                fma2(d0a, q[0][2][0], k2.x); fma2(d0a, q[0][2][1], k2.y);
                fma2(d1a, q[1][2][0], k2.x); fma2(d1a, q[1][2][1], k2.y);
                fma2(d0b, q[0][3][0], k3.x); fma2(d0b, q[0][3][1], k3.y);
                fma2(d1b, q[1][3][0], k3.x); fma2(d1b, q[1][3][1], k3.y);
                float xa, xb, ya, yb;
                up2(d0a, xa, xb); up2(d0b, ya, yb);
                float p0p = (xa + xb) + (ya + yb);      // head 2hg, my 16 d's
                up2(d1a, xa, xb); up2(d1b, ya, yb);
                float p1p = (xa + xb) + (ya + yb);      // head 2hg+1
                // role-swap: send the head I don't need; partner (xor1) has
                // flipped myh, so what I receive is my head's missing partial.
                float z = myh ? p0p : p1p;
                float mine = myh ? p1p : p0p;
                float tsum = mine + __shfl_xor_sync(~0u, z, 1);
                pm[kk] = tsum + __shfl_xor_sync(~0u, tsum, 2);
            }
            // -------- Phase B: exp * pe, gate --------
            float w[8];
            #pragma unroll
            for (int kk = 0; kk < 8; kk++) {
                float2 pg = *(const float2*)&pgb[(kb * 8 + kk) * 8];
                float pr = __expf(pm[kk]) * pg.x;
                s += pr;
                w[kk] = pr * pg.y;
            }
            // -------- Phase C: AV --------
            #pragma unroll
            for (int kk = 0; kk < 8; kk++) {
                const int kkk = kb * 8 + kk;
                float wo = __shfl_xor_sync(~0u, w[kk], 1);
                float wlo = myh ? wo : w[kk];
                float whi = myh ? w[kk] : wo;
                u64 wp0 = pk2(wlo, wlo), wp1 = pk2(whi, whi);
                const ulonglong2* vp = (const ulonglong2*)&kvb[kkk * 128 + 64 + dq * 4];
                ulonglong2 v0 = vp[0];
                ulonglong2 v1 = vp[4];
                ulonglong2 v2 = vp[8];
                ulonglong2 v3 = vp[12];
                fma2(acc[0][0][0], wp0, v0.x); fma2(acc[0][0][1], wp0, v0.y);
                fma2(acc[1][0][0], wp1, v0.x); fma2(acc[1][0][1], wp1, v0.y);
                fma2(acc[0][1][0], wp0, v1.x); fma2(acc[0][1][1], wp0, v1.y);
                fma2(acc[1][1][0], wp1, v1.x); fma2(acc[1][1][1], wp1, v1.y);
                fma2(acc[0][2][0], wp0, v2.x); fma2(acc[0][2][1], wp0, v2.y);
                fma2(acc[1][2][0], wp1, v2.x); fma2(acc[1][2][1], wp1, v2.y);
                fma2(acc[0][3][0], wp0, v3.x); fma2(acc[0][3][1], wp0, v3.y);
                fma2(acc[1][3][0], wp1, v3.x); fma2(acc[1][3][1], wp1, v3.y);
            }
        }
        __syncthreads();
    }
    #undef ISSUE_T

    // gather prob-sums for both local heads
    float so = __shfl_xor_sync(~0u, s, 1);
    float s0 = myh ? so : s;
    float s1 = myh ? s : so;
    float r0 = __fdividef(1.f, s0), r1 = __fdividef(1.f, s1);

    float* op = va + (size_t)(i * NN + j) * 512 + br * 4 + 2 * hg;
    #pragma unroll
    for (int u = 0; u < 4; u++) {
        int d0 = 16 * u + 4 * dq;
        float a, b;
        up2(acc[0][u][0], a, b);
        op[d0 * 8]           = tf32r(a * r0); op[(d0 + 1) * 8]     = tf32r(b * r0);
        up2(acc[0][u][1], a, b);
        op[(d0 + 2) * 8]     = tf32r(a * r0); op[(d0 + 3) * 8]     = tf32r(b * r0);
        up2(acc[1][u][0], a, b);
        op[d0 * 8 + 1]       = tf32r(a * r1); op[(d0 + 1) * 8 + 1] = tf32r(b * r1);
        up2(acc[1][u][1], a, b);
        op[(d0 + 2) * 8 + 1] = tf32r(a * r1); op[(d0 + 3) * 8 + 1] = tf32r(b * r1);
    }
}

// -------------------- launch -----------------------------------------------
extern "C" void kernel_launch(void* const* d_in, const int* in_sizes, int n_in,
                              void* d_out, int out_size) {
    const float* e       = (const float*)d_in[0];
    const float* mask    = (const float*)d_in[1];
    const float* ln_g    = (const float*)d_in[2];
    const float* ln_b    = (const float*)d_in[3];
    const float* Wq_in   = (const float*)d_in[4];
    const float* bq_in   = (const float*)d_in[5];
    const float* Wkv_in  = (const float*)d_in[6];
    const float* bkv_in  = (const float*)d_in[7];
    const float* Weg_in  = (const float*)d_in[8];
    const float* beg_in  = (const float*)d_in[9];
    const float* Wq_out  = (const float*)d_in[10];
    const float* bq_out  = (const float*)d_in[11];
    const float* Wkv_out = (const float*)d_in[12];
    const float* bkv_out = (const float*)d_in[13];
    const float* Weg_out = (const float*)d_in[14];
    const float* beg_out = (const float*)d_in[15];
    const float* Wo      = (const float*)d_in[16];
    const float* bo      = (const float*)d_in[17];
    float* out = (float*)d_out;

    float *p_eln, *p_wT1, *p_bcat, *p_proj, *p_va, *p_wT2, *p_egI, *p_egO;
    cudaGetSymbolAddress((void**)&p_eln,  g_eln);
    cudaGetSymbolAddress((void**)&p_wT1,  g_wT1);
    cudaGetSymbolAddress((void**)&p_bcat, g_bcat);
    cudaGetSymbolAddress((void**)&p_proj, g_proj);
    cudaGetSymbolAddress((void**)&p_va,   g_va);
    cudaGetSymbolAddress((void**)&p_wT2,  g_wT2);
    cudaGetSymbolAddress((void**)&p_egI,  g_egI);
    cudaGetSymbolAddress((void**)&p_egO,  g_egO);

    cudaFuncSetAttribute(tgemm, cudaFuncAttributeMaxDynamicSharedMemorySize, 65536);
    cudaFuncSetAttribute(attn_flash, cudaFuncAttributeMaxDynamicSharedMemorySize,
                         SM_FLOATS * 4);

    // 1. LayerNorm (warp per row, tf32-rounded out)
    ln_kernel<<<ROWS / 8, 256>>>(e, ln_g, ln_b);
    // 2. pack transposed weights (W1 + Wo in one launch)
    pack_w<<<1152, 256>>>(Wq_in, bq_in, Wkv_in, bkv_in, Weg_in, beg_in,
                          Wq_out, bq_out, Wkv_out, bkv_out, Weg_out, beg_out, Wo);
    // 3. projections: tf32 tensor-core GEMM [25600,256] @ [896,256]^T
    tgemm<<<dim3(7, ROWS / 128), 256, 65536>>>(p_eln, p_wT1, p_bcat, p_proj,
                                               EE, PC, PC);
    // 4a. precompute pe/gate tables (folds mask, exp, sigmoid)
    eg_tables<<<2 * ROWS / 256, 256>>>(p_proj, mask);
    // 4b. flash attention, phase-split mainloop
    attn_flash<<<dim3(NN, NN / 32, 2), 256, SM_FLOATS * 4>>>(p_proj, p_egI, p_egO, p_va);
    // 5. output projection: tf32 GEMM [25600,512] @ [256,512]^T -> d_out
    tgemm<<<dim3(2, ROWS / 128), 256, 65536>>>(p_va, p_wT2, bo, out,
                                               512, 256, 256);
}

// round 17
// speedup vs baseline: 2.7314x; 1.4224x over previous
#include <cuda_runtime.h>
#include <cuda_bf16.h>
#include <math.h>
#include <cstdint>

#define NN 160
#define EE 256
#define HH 4
#define DD 64
#define ROWS (NN*NN)          // 25600
#define PC 784                // packed projection cols
#define SCALE 0.125f
#define LN_EPS 1e-5f

// column offsets in packed projection
#define C_QIN   0
#define C_KIN   256
#define C_VIN   320
#define C_EGIN  384
#define C_QOUT  392
#define C_KOUT  648
#define C_VOUT  712
#define C_EGOUT 776

typedef unsigned long long u64;

__device__ __forceinline__ float tf32r(float x) {
    uint32_t u = __float_as_uint(x);
    asm("cvt.rna.tf32.f32 %0, %0;" : "+r"(u));
    return __uint_as_float(u);
}
__device__ __forceinline__ uint32_t smem_u32(const void* p) {
    uint32_t a;
    asm("{ .reg .u64 t; cvta.to.shared.u64 t, %1; cvt.u32.u64 %0, t; }" : "=r"(a) : "l"(p));
    return a;
}
__device__ __forceinline__ void sts32(uint32_t a, float v) {
    asm volatile("st.shared.f32 [%0], %1;" :: "r"(a), "f"(v));
}
#define SW(x) ((x) ^ (((x) >> 3) & 0x70))
#define LDMX4(r, a) asm volatile( \
    "ldmatrix.sync.aligned.m8n8.x4.shared.b16 {%0,%1,%2,%3}, [%4];" \
    : "=r"((r)[0]), "=r"((r)[1]), "=r"((r)[2]), "=r"((r)[3]) : "r"(a))
#define LDMX2(r, a) asm volatile( \
    "ldmatrix.sync.aligned.m8n8.x2.shared.b16 {%0,%1}, [%2];" \
    : "=r"((r)[0]), "=r"((r)[1]) : "r"(a))
__device__ __forceinline__ void mma_tf32(float* c, const uint32_t* a, const uint32_t* b) {
    asm volatile("mma.sync.aligned.m16n8k8.row.col.f32.tf32.tf32.f32 "
        "{%0,%1,%2,%3}, {%4,%5,%6,%7}, {%8,%9}, {%0,%1,%2,%3};"
        : "+f"(c[0]), "+f"(c[1]), "+f"(c[2]), "+f"(c[3])
        : "r"(a[0]), "r"(a[1]), "r"(a[2]), "r"(a[3]), "r"(b[0]), "r"(b[1]));
}
__device__ __forceinline__ void cpa16(uint32_t dst, const void* src) {
    asm volatile("cp.async.cg.shared.global [%0], [%1], 16;" :: "r"(dst), "l"(src));
}
#define CPA_COMMIT() asm volatile("cp.async.commit_group;" ::: "memory")

// -------------------- scratch ----------------------------------------------
__device__ float g_eln[ROWS * EE];
__device__ float g_wT1[896 * EE];
__device__ float g_bcat[896];
__device__ float g_proj[ROWS * PC];
__device__ float g_va[ROWS * 512];        // layout: [row][br][h][d]
__device__ float g_wT2[256 * 512];        // rows permuted to match
__device__ float g_egT[8 * ROWS * 2];     // [br][h][i*NN+k][2] = pe, gate

// -------------------- LayerNorm: warp per row -------------------------------
__global__ __launch_bounds__(256)
void ln_kernel(const float* __restrict__ e,
               const float* __restrict__ g,
               const float* __restrict__ b) {
    int wid = threadIdx.x >> 5, lane = threadIdx.x & 31;
    int r = blockIdx.x * 8 + wid;
    const float* er = e + (size_t)r * EE;
    float4 v0 = *(const float4*)(er + lane * 8);
    float4 v1 = *(const float4*)(er + lane * 8 + 4);
    float su = v0.x + v0.y + v0.z + v0.w + v1.x + v1.y + v1.z + v1.w;
    #pragma unroll
    for (int o = 16; o; o >>= 1) su += __shfl_xor_sync(~0u, su, o);
    float mu = su * (1.f / EE);
    float d0 = v0.x - mu, d1 = v0.y - mu, d2 = v0.z - mu, d3 = v0.w - mu;
    float d4 = v1.x - mu, d5 = v1.y - mu, d6 = v1.z - mu, d7 = v1.w - mu;
    float sq = d0*d0 + d1*d1 + d2*d2 + d3*d3 + d4*d4 + d5*d5 + d6*d6 + d7*d7;
    #pragma unroll
    for (int o = 16; o; o >>= 1) sq += __shfl_xor_sync(~0u, sq, o);
    float rs = rsqrtf(sq * (1.f / EE) + LN_EPS);
    float* orow = g_eln + (size_t)r * EE + lane * 8;
    const float* gp = g + lane * 8;
    const float* bp = b + lane * 8;
    float4 ga = *(const float4*)gp, gb2 = *(const float4*)(gp + 4);
    float4 ba = *(const float4*)bp, bb2 = *(const float4*)(bp + 4);
    float4 o0, o1;
    o0.x = tf32r(d0 * rs * ga.x + ba.x); o0.y = tf32r(d1 * rs * ga.y + ba.y);
    o0.z = tf32r(d2 * rs * ga.z + ba.z); o0.w = tf32r(d3 * rs * ga.w + ba.w);
    o1.x = tf32r(d4 * rs * gb2.x + bb2.x); o1.y = tf32r(d5 * rs * gb2.y + bb2.y);
    o1.z = tf32r(d6 * rs * gb2.z + bb2.z); o1.w = tf32r(d7 * rs * gb2.w + bb2.w);
    *(float4*)orow = o0;
    *(float4*)(orow + 4) = o1;
}

// -------------------- pack W1^T + permuted Wo^T -----------------------------
__global__ void pack_w(const float* __restrict__ Wq_in,  const float* __restrict__ bq_in,
                       const float* __restrict__ Wkv_in, const float* __restrict__ bkv_in,
                       const float* __restrict__ Weg_in, const float* __restrict__ beg_in,
                       const float* __restrict__ Wq_out, const float* __restrict__ bq_out,
                       const float* __restrict__ Wkv_out,const float* __restrict__ bkv_out,
                       const float* __restrict__ Weg_out,const float* __restrict__ beg_out,
                       const float* __restrict__ Wo) {
    int n = blockIdx.x;
    int k = threadIdx.x;
    if (n < 896) {
        float w = 0.f, bb = 0.f;
        if (n < 256)      { w = Wq_in [k*256 + n]        * SCALE; bb = bq_in [n]       * SCALE; }
        else if (n < 384) { w = Wkv_in[k*128 + (n-256)];          bb = bkv_in[n-256]; }
        else if (n < 392) { w = Weg_in[k*8   + (n-384)];          bb = beg_in[n-384]; }
        else if (n < 648) { w = Wq_out[k*256 + (n-392)]  * SCALE; bb = bq_out[n-392]  * SCALE; }
        else if (n < 776) { w = Wkv_out[k*128 + (n-648)];         bb = bkv_out[n-648]; }
        else if (n < 784) { w = Weg_out[k*8  + (n-776)];          bb = beg_out[n-776]; }
        g_wT1[(size_t)n * EE + k] = tf32r(w);
        if (k == 0) g_bcat[n] = bb;
    } else {
        int n2 = n - 896;   // 0..255
        #pragma unroll
        for (int t = 0; t < 2; t++) {
            int cp = k + t * 256;                 // permuted channel
            int d = cp & 63, hh = (cp >> 6) & 3, bb = cp >> 8;
            int c = d * 8 + bb * 4 + hh;          // original channel
            g_wT2[(size_t)n2 * 512 + cp] = tf32r(Wo[c * 256 + n2]);
        }
    }
}

// -------------------- EG -> pe/gate tables, head-planar ---------------------
__global__ void eg_tables(const float* __restrict__ proj, const float* __restrict__ mask) {
    int gid = blockIdx.x * 256 + threadIdx.x;     // 0..51199
    int br = gid >= ROWS;
    int rem = br ? gid - ROWS : gid;
    int i = rem / NN, k = rem % NN;
    int row = br ? (k * NN + i) : (i * NN + k);
    const float* p = proj + (size_t)row * PC + (br ? C_EGOUT : C_EGIN);
    float4 E = *(const float4*)p;
    float4 G = *(const float4*)(p + 4);
    float mk = mask[row];
    float2* eg2 = (float2*)g_egT;
    size_t base = (size_t)(br * 4) * ROWS + rem;
    eg2[base]            = make_float2(__expf(E.x + mk), __fdividef(1.f, 1.f + __expf(-(G.x + mk))));
    eg2[base + ROWS]     = make_float2(__expf(E.y + mk), __fdividef(1.f, 1.f + __expf(-(G.y + mk))));
    eg2[base + 2*ROWS]   = make_float2(__expf(E.z + mk), __fdividef(1.f, 1.f + __expf(-(G.z + mk))));
    eg2[base + 3*ROWS]   = make_float2(__expf(E.w + mk), __fdividef(1.f, 1.f + __expf(-(G.w + mk))));
}

// -------------------- tf32 tensor-core GEMM ---------------------------------
__global__ __launch_bounds__(256, 2)
void tgemm(const float* __restrict__ A, const float* __restrict__ Bt,
           const float* __restrict__ bias, float* __restrict__ C,
           int K, int NC, int Nvalid, int roundC) {
    extern __shared__ __align__(1024) char dsm[];
    const int tid = threadIdx.x, lid = tid & 31, wid = tid >> 5;
    const int wr = wid >> 2, wc = wid & 3;
    const int bm = blockIdx.y * 128, bn = blockIdx.x * 128;
    const uint32_t smBase = smem_u32(dsm);

    float acc[4][4][4];
    #pragma unroll
    for (int mt = 0; mt < 4; mt++)
        #pragma unroll
        for (int nt = 0; nt < 4; nt++)
            #pragma unroll
            for (int q = 0; q < 4; q++) acc[mt][nt][q] = 0.f;

    const int nck = K >> 5;

    #define ISSUE(ck, buf) do { \
        const float* Ab_ = A + (size_t)bm * K + (ck) * 32; \
        const float* Bb_ = Bt + (size_t)bn * K + (ck) * 32; \
        uint32_t aD_ = smBase + (buf) * 32768; \
        uint32_t bD_ = aD_ + 16384; \
        _Pragma("unroll") \
        for (int l_ = 0; l_ < 4; l_++) { \
            int idx_ = tid + l_ * 256; \
            int r_ = idx_ >> 3, c_ = idx_ & 7; \
            int off_ = r_ * 128 + c_ * 16; \
            off_ ^= (off_ >> 3) & 0x70; \
            cpa16(aD_ + off_, Ab_ + (size_t)r_ * K + c_ * 4); \
            cpa16(bD_ + off_, Bb_ + (size_t)r_ * K + c_ * 4); \
        } \
        CPA_COMMIT(); \
    } while (0)

    ISSUE(0, 0);
    for (int ck = 0; ck < nck; ck++) {
        const int buf = ck & 1;
        if (ck + 1 < nck) {
            ISSUE(ck + 1, buf ^ 1);
            asm volatile("cp.async.wait_group 1;" ::: "memory");
        } else {
            asm volatile("cp.async.wait_group 0;" ::: "memory");
        }
        __syncthreads();

        const uint32_t aW = smBase + buf * 32768 + (wr * 64) * 128;
        const uint32_t bW = smBase + buf * 32768 + 16384 + (wc * 32) * 128;
        #pragma unroll
        for (int ks = 0; ks < 4; ks++) {
            uint32_t afr[4][4], bfr[4][2];
            #pragma unroll
            for (int mt = 0; mt < 4; mt++) {
                int off = (mt * 16 + (lid & 15)) * 128 + (ks * 2 + (lid >> 4)) * 16;
                off ^= (off >> 3) & 0x70;
                LDMX4(afr[mt], aW + off);
            }
            #pragma unroll
            for (int nt = 0; nt < 4; nt++) {
                int off = (nt * 8 + (lid & 7)) * 128 + (ks * 2 + ((lid >> 3) & 1)) * 16;
                off ^= (off >> 3) & 0x70;
                LDMX2(bfr[nt], bW + off);
            }
            #pragma unroll
            for (int mt = 0; mt < 4; mt++)
                #pragma unroll
                for (int nt = 0; nt < 4; nt++)
                    mma_tf32(acc[mt][nt], afr[mt], bfr[nt]);
        }
        __syncthreads();
    }
    #undef ISSUE

    #pragma unroll
    for (int mt = 0; mt < 4; mt++) {
        int row0 = bm + wr * 64 + mt * 16 + (lid >> 2);
        #pragma unroll
        for (int nt = 0; nt < 4; nt++) {
            int col0 = bn + wc * 32 + nt * 8 + (lid & 3) * 2;
            if (col0 < Nvalid) {
                float v0 = acc[mt][nt][0] + bias[col0];
                float v1 = acc[mt][nt][1] + bias[col0 + 1];
                float v2 = acc[mt][nt][2] + bias[col0];
                float v3 = acc[mt][nt][3] + bias[col0 + 1];
                if (roundC) { v0 = tf32r(v0); v1 = tf32r(v1); v2 = tf32r(v2); v3 = tf32r(v3); }
                C[(size_t)row0 * NC + col0]           = v0;
                C[(size_t)row0 * NC + col0 + 1]       = v1;
                C[(size_t)(row0 + 8) * NC + col0]     = v2;
                C[(size_t)(row0 + 8) * NC + col0 + 1] = v3;
            }
        }
    }
}

// -------------------- MMA attention -----------------------------------------
// block = (j, ic, br); 8 warps (mw = wid>>2 in {0,1}: 16-i tile; nw = wid&3: k/d split)
// smem bytes: K 0..40960 (2 panels [160][128B])
//             VT 40960..81920 (5 panels [64][128B], transposed V)
//             Q 81920..114688 (4 heads x 2 panels [32][128B])
//             P 114688..135168 (5 panels [32][128B])
//             PG 135168..218112 (2 bufs x [32][324 floats][pe,g])
//             SPART 218112 (4x32 f), RS 218624 (32 f)  -> total 218752 B
#define AT_SMEM 218752
__global__ __launch_bounds__(256, 1)
void attn_mma(const float* __restrict__ proj, const float* __restrict__ egT,
              float* __restrict__ va) {
    extern __shared__ __align__(16) float sm[];
    const int j = blockIdx.x, ic = blockIdx.y, br = blockIdx.z;
    const int tid = threadIdx.x, lid = tid & 31, wid = tid >> 5;
    const int mw = wid >> 2, nw = wid & 3;
    const int KVB = br ? C_KOUT : C_KIN;
    const int QB  = br ? C_QOUT : C_QIN;
    const uint32_t smB = smem_u32(sm);
    const uint32_t OK_ = 0, OVT = 40960, OQ = 81920, OP = 114688, OPG = 135168;
    const int FPG = 33792, FSP = 54528, FRS = 54656;

    // ---- stage K via cp.async: 160 rows x 64 d -> 2 swizzled panels ----
    // (16 cpa16 per row: c = 0..15, panel = c>>3, col = (c&7)*16 bytes)
    for (int idx = tid; idx < 2560; idx += 256) {
        int r = idx >> 4, c = idx & 15;
        int row = br ? (r * NN + j) : (j * NN + r);
        int rel = SW(r * 128 + (c & 7) * 16);
        cpa16(smB + OK_ + (c >> 3) * 20480 + rel,
              proj + (size_t)row * PC + KVB + c * 4);
    }
    CPA_COMMIT();
    // ---- stage pg for head 0 ----
    {
        const float* src = egT + ((size_t)(br * 4) * ROWS + (size_t)(ic * 32) * NN) * 2;
        int iL = tid >> 3;
        uint32_t dstb = smB + OPG + iL * 1296;
        #pragma unroll
        for (int cc = 0; cc < 10; cc++) {
            int c = (tid & 7) + cc * 8;
            cpa16(dstb + c * 16, src + (size_t)iL * (NN * 2) + c * 4);
        }
    }
    CPA_COMMIT();
    // ---- stage V^T (scalar transpose) ----
    for (int idx = tid; idx < 2560; idx += 256) {
        int k = idx >> 4, c = idx & 15;
        int row = br ? (k * NN + j) : (j * NN + k);
        float4 v = *(const float4*)(proj + (size_t)row * PC + KVB + 64 + c * 4);
        uint32_t pb = smB + OVT + (k >> 5) * 8192;
        int kk = (k & 31) * 4;
        sts32(pb + SW((c * 4 + 0) * 128 + kk), v.x);
        sts32(pb + SW((c * 4 + 1) * 128 + kk), v.y);
        sts32(pb + SW((c * 4 + 2) * 128 + kk), v.z);
        sts32(pb + SW((c * 4 + 3) * 128 + kk), v.w);
    }
    // ---- stage Q (scalar head de-interleave) ----
    for (int idx = tid; idx < 2048; idx += 256) {
        int i = idx >> 6, c = idx & 63;
        int row = (ic * 32 + i) * NN + j;
        float4 v = *(const float4*)(proj + (size_t)row * PC + QB + c * 4);
        int rel = SW(i * 128 + (c & 31) * 4);
        uint32_t base = smB + OQ + (c >> 5) * 4096 + rel;
        sts32(base,         v.x);
        sts32(base + 8192,  v.y);
        sts32(base + 16384, v.z);
        sts32(base + 24576, v.w);
    }
    asm volatile("cp.async.wait_group 0;" ::: "memory");
    __syncthreads();

    const int r0 = mw * 16 + (lid >> 2);
    #pragma unroll 1
    for (int h = 0; h < 4; h++) {
        // prefetch next head's pe/gate tile
        if (h < 3) {
            const float* src = egT + ((size_t)(br * 4 + h + 1) * ROWS
                                      + (size_t)(ic * 32) * NN) * 2;
            int iL = tid >> 3;
            uint32_t dstb = smB + OPG + ((h + 1) & 1) * 41472 + iL * 1296;
            #pragma unroll
            for (int cc = 0; cc < 10; cc++) {
                int c = (tid & 7) + cc * 8;
                cpa16(dstb + c * 16, src + (size_t)iL * (NN * 2) + c * 4);
            }
            CPA_COMMIT();
        }
        // ---- QK: S[i,k] frags ----
        uint32_t a[8][4];
        #pragma unroll
        for (int ks = 0; ks < 8; ks++) {
            int rel = SW((mw * 16 + (lid & 15)) * 128 + ((ks & 3) * 2 + (lid >> 4)) * 16);
            LDMX4(a[ks], smB + OQ + h * 8192 + (ks >> 2) * 4096 + rel);
        }
        float c5[5][4];
        #pragma unroll
        for (int nt = 0; nt < 5; nt++) {
            c5[nt][0] = c5[nt][1] = c5[nt][2] = c5[nt][3] = 0.f;
            #pragma unroll
            for (int ks = 0; ks < 8; ks++) {
                uint32_t b[2];
                int rel = SW((nw * 40 + nt * 8 + (lid & 7)) * 128
                             + ((ks & 3) * 2 + ((lid >> 3) & 1)) * 16);
                LDMX2(b, smB + OK_ + (ks >> 2) * 20480 + rel);
                mma_tf32(c5[nt], a[ks], b);
            }
        }
        if (h) {
            if (h < 3) asm volatile("cp.async.wait_group 1;" ::: "memory");
            else       asm volatile("cp.async.wait_group 0;" ::: "memory");
            __syncthreads();     // pg(h) visible; prior head fully done
        }
        // ---- softmax + gate -> P ----
        const float* pgf = sm + FPG + (h & 1) * 10368;
        float s0 = 0.f, s1 = 0.f;
        #pragma unroll
        for (int nt = 0; nt < 5; nt++) {
            int k0 = nw * 40 + nt * 8 + (lid & 3) * 2;
            float4 pg0 = *(const float4*)&pgf[r0 * 324 + k0 * 2];
            float4 pg1 = *(const float4*)&pgf[(r0 + 8) * 324 + k0 * 2];
            float pr0 = __expf(c5[nt][0]) * pg0.x;
            float pr1 = __expf(c5[nt][1]) * pg0.z;
            float pr2 = __expf(c5[nt][2]) * pg1.x;
            float pr3 = __expf(c5[nt][3]) * pg1.z;
            s0 += pr0 + pr1; s1 += pr2 + pr3;
            uint32_t pb = smB + OP + (k0 >> 5) * 4096;
            int kk = (k0 & 31) * 4;
            sts32(pb + SW(r0 * 128 + kk),          tf32r(pr0 * pg0.y));
            sts32(pb + SW(r0 * 128 + kk + 4),      tf32r(pr1 * pg0.w));
            sts32(pb + SW((r0 + 8) * 128 + kk),    tf32r(pr2 * pg1.y));
            sts32(pb + SW((r0 + 8) * 128 + kk + 4),tf32r(pr3 * pg1.w));
        }
        s0 += __shfl_xor_sync(~0u, s0, 1); s0 += __shfl_xor_sync(~0u, s0, 2);
        s1 += __shfl_xor_sync(~0u, s1, 1); s1 += __shfl_xor_sync(~0u, s1, 2);
        if ((lid & 3) == 0) {
            sm[FSP + nw * 32 + r0]     = s0;
            sm[FSP + nw * 32 + r0 + 8] = s1;
        }
        __syncthreads();        // P + partials complete
        if (tid < 32) {
            float t = sm[FSP + tid] + sm[FSP + 32 + tid]
                    + sm[FSP + 64 + tid] + sm[FSP + 96 + tid];
            sm[FRS + tid] = __fdividef(1.f, t);
        }
        // ---- AV: Va[i,d] frags ----
        float acc0[4] = {0, 0, 0, 0}, acc1[4] = {0, 0, 0, 0};
        #pragma unroll
        for (int kc = 0; kc < 20; kc++) {
            uint32_t pa[4], pb0[2], pb1[2];
            int relA = SW((mw * 16 + (lid & 15)) * 128 + ((kc & 3) * 2 + (lid >> 4)) * 16);
            LDMX4(pa, smB + OP + (kc >> 2) * 4096 + relA);
            int cb = ((kc & 3) * 2 + ((lid >> 3) & 1)) * 16;
            LDMX2(pb0, smB + OVT + (kc >> 2) * 8192 + SW(((nw * 2) * 8 + (lid & 7)) * 128 + cb));
            LDMX2(pb1, smB + OVT + (kc >> 2) * 8192 + SW(((nw * 2 + 1) * 8 + (lid & 7)) * 128 + cb));
            mma_tf32(acc0, pa, pb0);
            mma_tf32(acc1, pa, pb1);
        }
        __syncthreads();        // rs visible; all AV reads of P done
        // ---- epilogue ----
        float ri0 = sm[FRS + r0], ri1 = sm[FRS + r0 + 8];
        int d0 = (nw * 2) * 8 + (lid & 3) * 2;
        size_t ro0 = (size_t)((ic * 32 + r0) * NN + j) * 512 + br * 256 + h * 64;
        size_t ro1 = (size_t)((ic * 32 + r0 + 8) * NN + j) * 512 + br * 256 + h * 64;
        float2 o;
        o.x = tf32r(acc0[0] * ri0); o.y = tf32r(acc0[1] * ri0);
        *(float2*)&va[ro0 + d0] = o;
        o.x = tf32r(acc0[2] * ri1); o.y = tf32r(acc0[3] * ri1);
        *(float2*)&va[ro1 + d0] = o;
        o.x = tf32r(acc1[0] * ri0); o.y = tf32r(acc1[1] * ri0);
        *(float2*)&va[ro0 + d0 + 8] = o;
        o.x = tf32r(acc1[2] * ri1); o.y = tf32r(acc1[3] * ri1);
        *(float2*)&va[ro1 + d0 + 8] = o;
    }
}

// -------------------- launch -----------------------------------------------
extern "C" void kernel_launch(void* const* d_in, const int* in_sizes, int n_in,
                              void* d_out, int out_size) {
    const float* e       = (const float*)d_in[0];
    const float* mask    = (const float*)d_in[1];
    const float* ln_g    = (const float*)d_in[2];
    const float* ln_b    = (const float*)d_in[3];
    const float* Wq_in   = (const float*)d_in[4];
    const float* bq_in   = (const float*)d_in[5];
    const float* Wkv_in  = (const float*)d_in[6];
    const float* bkv_in  = (const float*)d_in[7];
    const float* Weg_in  = (const float*)d_in[8];
    const float* beg_in  = (const float*)d_in[9];
    const float* Wq_out  = (const float*)d_in[10];
    const float* bq_out  = (const float*)d_in[11];
    const float* Wkv_out = (const float*)d_in[12];
    const float* bkv_out = (const float*)d_in[13];
    const float* Weg_out = (const float*)d_in[14];
    const float* beg_out = (const float*)d_in[15];
    const float* Wo      = (const float*)d_in[16];
    const float* bo      = (const float*)d_in[17];
    float* out = (float*)d_out;

    float *p_eln, *p_wT1, *p_bcat, *p_proj, *p_va, *p_wT2, *p_egT;
    cudaGetSymbolAddress((void**)&p_eln,  g_eln);
    cudaGetSymbolAddress((void**)&p_wT1,  g_wT1);
    cudaGetSymbolAddress((void**)&p_bcat, g_bcat);
    cudaGetSymbolAddress((void**)&p_proj, g_proj);
    cudaGetSymbolAddress((void**)&p_va,   g_va);
    cudaGetSymbolAddress((void**)&p_wT2,  g_wT2);
    cudaGetSymbolAddress((void**)&p_egT,  g_egT);

    cudaFuncSetAttribute(tgemm, cudaFuncAttributeMaxDynamicSharedMemorySize, 65536);
    cudaFuncSetAttribute(attn_mma, cudaFuncAttributeMaxDynamicSharedMemorySize, AT_SMEM);

    // 1. LayerNorm
    ln_kernel<<<ROWS / 8, 256>>>(e, ln_g, ln_b);
    // 2. pack weights (W1 + permuted Wo)
    pack_w<<<1152, 256>>>(Wq_in, bq_in, Wkv_in, bkv_in, Weg_in, beg_in,
                          Wq_out, bq_out, Wkv_out, bkv_out, Weg_out, beg_out, Wo);
    // 3. projections (tf32-rounded output for MMA attention)
    tgemm<<<dim3(7, ROWS / 128), 256, 65536>>>(p_eln, p_wT1, p_bcat, p_proj,
                                               EE, PC, PC, 1);
    // 4a. pe/gate tables (head-planar layout)
    eg_tables<<<2 * ROWS / 256, 256>>>(p_proj, mask);
    // 4b. MMA attention
    attn_mma<<<dim3(NN, NN / 32, 2), 256, AT_SMEM>>>(p_proj, p_egT, p_va);
    // 5. output projection
    tgemm<<<dim3(2, ROWS / 128), 256, 65536>>>(p_va, p_wT2, bo, out,
                                               512, 256, 256, 0);
}